// round 10
// baseline (speedup 1.0000x reference)
#include <cuda_runtime.h>
#include <cuda_bf16.h>
#include <cstdint>
#include <cstddef>

// Problem dims
#define BDIM 4096
#define TDIM 128
#define DDIM 64
#define HDIM 100
#define G4   400          // 4*H
#define NCLS 8
#define M1   (BDIM * TDIM)   // 524288 rows

// ---------------- scratch (device globals; no allocation allowed) ----------
__device__ __align__(16) float g_xp[(size_t)M1 * G4];     // 800 MB, reused by both layers
__device__ __align__(16) float g_last[BDIM * HDIM];       // relu(h_T) of layer 2
// bf16 hi/lo inputs for the two projection GEMMs
__device__ __align__(16) __nv_bfloat16 g_xhi[(size_t)M1 * 64];    // layer-1 x hi
__device__ __align__(16) __nv_bfloat16 g_xlo[(size_t)M1 * 64];    // layer-1 x lo
__device__ __align__(16) __nv_bfloat16 g_hhi[(size_t)M1 * 112];   // layer-2 in hi (relu h1), K padded to 112
__device__ __align__(16) __nv_bfloat16 g_hlo[(size_t)M1 * 112];   // layer-2 in lo

// ---------------- helpers ----------------
__device__ __forceinline__ float sigm(float x) {
    return __fdividef(1.0f, 1.0f + __expf(-x));
}
__device__ __forceinline__ uint32_t pack_bf2(float a, float b) {
    __nv_bfloat162 p = __floats2bfloat162_rn(a, b);
    return *reinterpret_cast<uint32_t*>(&p);
}
__device__ __forceinline__ uint32_t smem_u32(const void* p) {
    uint32_t a;
    asm("{ .reg .u64 t; cvta.to.shared.u64 t, %1; cvt.u32.u64 %0, t; }" : "=r"(a) : "l"(p));
    return a;
}

// m16n8k16 row.col bf16 MMA with fp32 accumulate (HMMA on Blackwell)
__device__ __forceinline__ void mma16816(float c[4], const uint32_t a[4], const uint32_t b[2]) {
    asm volatile(
        "mma.sync.aligned.m16n8k16.row.col.f32.bf16.bf16.f32 "
        "{%0,%1,%2,%3}, {%4,%5,%6,%7}, {%8,%9}, {%0,%1,%2,%3};"
        : "+f"(c[0]), "+f"(c[1]), "+f"(c[2]), "+f"(c[3])
        : "r"(a[0]), "r"(a[1]), "r"(a[2]), "r"(a[3]), "r"(b[0]), "r"(b[1]));
}

#define LDSM_X4(r, addr) \
    asm volatile("ldmatrix.sync.aligned.m8n8.x4.shared.b16 {%0,%1,%2,%3}, [%4];" \
        : "=r"((r)[0]), "=r"((r)[1]), "=r"((r)[2]), "=r"((r)[3]) : "r"(addr))

__device__ __forceinline__ void cp16(uint32_t dst, const void* src) {
    asm volatile("cp.async.cg.shared.global [%0], [%1], 16;" :: "r"(dst), "l"(src));
}
#define CP_COMMIT() asm volatile("cp.async.commit_group;" ::: "memory")
#define CP_WAIT1()  asm volatile("cp.async.wait_group 1;" ::: "memory")

// ======================================================================
// Prepass: x fp32 -> g_xhi/g_xlo bf16; zero pad cols 100..111 of g_hhi/g_hlo
// ======================================================================
__global__ void prep_kernel(const float* __restrict__ x)
{
    const size_t stride = (size_t)gridDim.x * blockDim.x;
    const size_t gt = (size_t)blockIdx.x * blockDim.x + threadIdx.x;

    const size_t N4 = (size_t)M1 * 64 / 4;
    const float4* x4 = (const float4*)x;
    uint2* oh = (uint2*)g_xhi;
    uint2* ol = (uint2*)g_xlo;
    for (size_t i = gt; i < N4; i += stride) {
        float4 v = x4[i];
        float h0 = __bfloat162float(__float2bfloat16(v.x));
        float h1 = __bfloat162float(__float2bfloat16(v.y));
        float h2 = __bfloat162float(__float2bfloat16(v.z));
        float h3 = __bfloat162float(__float2bfloat16(v.w));
        oh[i] = make_uint2(pack_bf2(h0, h1), pack_bf2(h2, h3));
        ol[i] = make_uint2(pack_bf2(v.x - h0, v.y - h1), pack_bf2(v.z - h2, v.w - h3));
    }
    // zero pad columns 100..111 (6 uint32 per row per array)
    const size_t NP = (size_t)M1 * 6;
    for (size_t i = gt; i < NP; i += stride) {
        size_t r = i / 6;
        int j = (int)(i - r * 6);
        ((uint32_t*)((char*)g_hhi + r * 224 + 200))[j] = 0;
        ((uint32_t*)((char*)g_hlo + r * 224 + 200))[j] = 0;
    }
}

// ======================================================================
// Input-projection GEMM v2: g_xp = [Xhi+Xlo] @ W^T + (ba+bb)
// All-compute 256-thread CTAs, cp.async double-buffered bf16 tiles,
// ldmatrix.x4 fragment loads. Gate-interleaved output (col' = unit*4+gate).
// KG = padded global K / row stride; SKPX = smem row stride; KSTEPS = K/16.
// ======================================================================
template <int KG, int SKPX, int KSTEPS>
__global__ __launch_bounds__(256) void xproj_mma2(
    const __nv_bfloat16* __restrict__ Xhi, const __nv_bfloat16* __restrict__ Xlo,
    const float* __restrict__ W, int Kw,
    const float* __restrict__ ba, const float* __restrict__ bb)
{
    constexpr int NH  = 200;
    constexpr int NWR = 208;                 // padded W rows (ldmatrix x4 overread)
    constexpr int WB  = NWR * SKPX * 2;
    constexpr int XB  = 128 * SKPX * 2;
    constexpr int NCH = KG / 8;              // 16B chunks per row

    extern __shared__ char sm[];
    float* bs = (float*)sm;                  // [200] bias
    char* WhiP = sm + 1024;

    const int tid  = threadIdx.x;
    const int wid  = tid >> 5;
    const int lane = tid & 31;
    const int g    = lane >> 2;
    const int t4   = lane & 3;
    const int hf   = blockIdx.x & 1;
    const int cta  = blockIdx.x >> 1;

    const uint32_t smb  = smem_u32(sm);
    const uint32_t wh_b = smb + 1024;
    const uint32_t wl_b = wh_b + (uint32_t)WB;
    const uint32_t x_b  = wh_b + 2u * (uint32_t)WB;

    // zero W buffers (covers K padding)
    {
        uint32_t* z = (uint32_t*)WhiP;
        for (int i = tid; i < 2 * WB / 4; i += 256) z[i] = 0;
    }
    __syncthreads();

    // convert W (hi/lo) + bias; smem slot n <-> W row gate*100 + (hf*50 + n/4)
    {
        const int KQ = Kw / 4;
        char* Whi = WhiP;
        char* Wlo = WhiP + WB;
        for (int i4 = tid; i4 < NH * KQ; i4 += 256) {
            int n = i4 / KQ, kq = i4 - n * KQ;
            int unit = hf * 50 + (n >> 2);
            int gate = n & 3;
            float4 v = *(const float4*)(W + (size_t)(gate * HDIM + unit) * Kw + kq * 4);
            float h0 = __bfloat162float(__float2bfloat16(v.x));
            float h1 = __bfloat162float(__float2bfloat16(v.y));
            float h2 = __bfloat162float(__float2bfloat16(v.z));
            float h3 = __bfloat162float(__float2bfloat16(v.w));
            uint32_t* ph = (uint32_t*)(Whi + (n * SKPX + kq * 4) * 2);
            uint32_t* pl = (uint32_t*)(Wlo + (n * SKPX + kq * 4) * 2);
            ph[0] = pack_bf2(h0, h1);
            ph[1] = pack_bf2(h2, h3);
            pl[0] = pack_bf2(v.x - h0, v.y - h1);
            pl[1] = pack_bf2(v.z - h2, v.w - h3);
        }
        for (int n = tid; n < NH; n += 256) {
            int wrow = (n & 3) * HDIM + hf * 50 + (n >> 2);
            bs[n] = ba[wrow] + bb[wrow];
        }
    }

    auto issue = [&](int tile, int p) {
        uint32_t dh = x_b + (uint32_t)p * (2u * XB);
        uint32_t dl = dh + (uint32_t)XB;
        const __nv_bfloat16* sh = Xhi + (size_t)tile * 128 * KG;
        const __nv_bfloat16* sl = Xlo + (size_t)tile * 128 * KG;
        for (int i = tid; i < 128 * NCH; i += 256) {
            int r = i / NCH, c = i - r * NCH;
            uint32_t doff = (uint32_t)(r * SKPX + c * 8) * 2;
            size_t soff = (size_t)r * KG + c * 8;
            cp16(dh + doff, sh + soff);
            cp16(dl + doff, sl + soff);
        }
    };

    issue(cta, 0);
    CP_COMMIT();

    const int m0 = wid * 16;
    const uint32_t a_off = (uint32_t)((m0 + (lane & 7) + ((lane >> 3) & 1) * 8) * SKPX * 2
                                      + ((lane >> 4) & 1) * 16);
    const uint32_t b_off = (uint32_t)(((lane & 7) + ((lane >> 4) & 1) * 8) * SKPX * 2
                                      + ((lane >> 3) & 1) * 16);

    int par = 0;
    for (int tile = cta; tile < 4096; tile += 74) {
        __syncthreads();                 // buf[par^1] free (previous compute done)
        int nt2 = tile + 74;
        if (nt2 < 4096) issue(nt2, par ^ 1);
        CP_COMMIT();
        CP_WAIT1();                      // buf[par] group complete (this thread)
        __syncthreads();                 // ... and for all threads

        float C[25][4];
        #pragma unroll
        for (int nt = 0; nt < 25; nt++)
            #pragma unroll
            for (int j = 0; j < 4; j++) C[nt][j] = 0.0f;

        const uint32_t axh = x_b + (uint32_t)par * (2u * XB) + a_off;
        const uint32_t axl = axh + (uint32_t)XB;

        #pragma unroll
        for (int ks = 0; ks < KSTEPS; ks++) {
            uint32_t ah[4], al[4];
            LDSM_X4(ah, axh + ks * 32);
            LDSM_X4(al, axl + ks * 32);
            #pragma unroll
            for (int ntp = 0; ntp < 13; ntp++) {
                uint32_t bh[4], bl[4];
                uint32_t bo = b_off + (uint32_t)(ntp * 16 * SKPX * 2) + ks * 32;
                LDSM_X4(bh, wh_b + bo);
                LDSM_X4(bl, wl_b + bo);
                mma16816(C[2 * ntp], ah, bh);
                mma16816(C[2 * ntp], al, bh);
                mma16816(C[2 * ntp], ah, bl);
                if (2 * ntp + 1 < 25) {
                    mma16816(C[2 * ntp + 1], ah, bh + 2);
                    mma16816(C[2 * ntp + 1], al, bh + 2);
                    mma16816(C[2 * ntp + 1], ah, bl + 2);
                }
            }
        }

        // epilogue: add bias, store fp32
        float* out0 = g_xp + (size_t)(tile * 128 + m0 + g) * G4 + hf * NH;
        float* out1 = out0 + 8 * G4;
        #pragma unroll
        for (int nt = 0; nt < 25; nt++) {
            int col = nt * 8 + t4 * 2;
            float2 b2 = *(float2*)(bs + col);
            *(float2*)(out0 + col) = make_float2(C[nt][0] + b2.x, C[nt][1] + b2.y);
            *(float2*)(out1 + col) = make_float2(C[nt][2] + b2.x, C[nt][3] + b2.y);
        }
        par ^= 1;
    }
}

// ======================================================================
// Tensor-core recurrent scan (R6 structure, proven).
// mode 1: write relu(h) as bf16 hi/lo into g_hhi/g_hlo (K padded 112).
// mode 2: write relu(h_T) fp32 into g_last.
// ======================================================================
#define SKP 120                      // smem K stride (elements)
#define SWB (G4 * SKP * 2)           // 96000 B per W buffer
#define SAB (32 * SKP * 2)           // 7680 B per h buffer

__global__ __launch_bounds__(512) void lstm_scan_mma(
    const float* __restrict__ Whh, int mode)
{
    extern __shared__ char sm[];
    char* Whi   = sm;
    char* Wlo   = Whi + SWB;
    char* Abase = Wlo + SWB;         // 2 parity buffers x (hi, lo)

    const int tid  = threadIdx.x;
    const int wid  = tid >> 5;
    const int lane = tid & 31;
    const int g    = lane >> 2;
    const int t4   = lane & 3;
    const int b0   = blockIdx.x * 32;

    {
        uint32_t* z = (uint32_t*)sm;
        int tot = (2 * SWB + 4 * SAB) / 4;
        for (int i = tid; i < tot; i += 512) z[i] = 0;
    }
    __syncthreads();

    for (int i4 = tid; i4 < G4 * (HDIM / 4); i4 += 512) {
        int n = i4 / (HDIM / 4), kq = i4 - n * (HDIM / 4);
        int unit = n >> 2, gate = n & 3;
        float4 v = *(const float4*)(Whh + (size_t)(gate * HDIM + unit) * HDIM + kq * 4);
        float h0 = __bfloat162float(__float2bfloat16(v.x));
        float h1 = __bfloat162float(__float2bfloat16(v.y));
        float h2 = __bfloat162float(__float2bfloat16(v.z));
        float h3 = __bfloat162float(__float2bfloat16(v.w));
        uint32_t* ph = (uint32_t*)(Whi + (n * SKP + kq * 4) * 2);
        uint32_t* pl = (uint32_t*)(Wlo + (n * SKP + kq * 4) * 2);
        ph[0] = pack_bf2(h0, h1);
        ph[1] = pack_bf2(h2, h3);
        pl[0] = pack_bf2(v.x - h0, v.y - h1);
        pl[1] = pack_bf2(v.z - h2, v.w - h3);
    }
    __syncthreads();

    const uint32_t* Wh32 = (const uint32_t*)Whi;
    const uint32_t* Wl32 = (const uint32_t*)Wlo;

    const int mi     = wid & 1;
    const int ncol   = wid >> 1;                    // 0..7
    const int m0     = mi * 16;
    const int NT     = (ncol < 2) ? 7 : 6;
    const int tstart = (ncol < 2) ? ncol * 7 : 14 + (ncol - 2) * 6;
    const bool evn   = (t4 & 1) == 0;

    const int row0 = m0 + g;
    const int row1 = row0 + 8;

    float c[7][2];
    #pragma unroll
    for (int nt = 0; nt < 7; nt++) { c[nt][0] = 0.0f; c[nt][1] = 0.0f; }

    const int nbase = (tstart * 8 + g) * (SKP / 2) + t4;   // uint32 units
    const __nv_bfloat16 zbf = __float2bfloat16(0.0f);

    int par = 0;
    for (int t = 0; t < TDIM; t++) {
        const uint32_t* Ah32 = (const uint32_t*)(Abase + par * (2 * SAB));
        const uint32_t* Al32 = Ah32 + SAB / 4;
        __nv_bfloat16* AhW = (__nv_bfloat16*)(Abase + (par ^ 1) * (2 * SAB));
        __nv_bfloat16* AlW = AhW + SAB / 2;

        float C[7][4];
        {
            const float* p0 = g_xp + ((size_t)(b0 + row0) * TDIM + t) * G4 + tstart * 8 + t4 * 2;
            const float* p1 = g_xp + ((size_t)(b0 + row1) * TDIM + t) * G4 + tstart * 8 + t4 * 2;
            #pragma unroll
            for (int nt = 0; nt < 7; nt++) {
                if (nt < NT) {
                    float2 v0 = *(const float2*)(p0 + nt * 8);
                    float2 v1 = *(const float2*)(p1 + nt * 8);
                    C[nt][0] = v0.x; C[nt][1] = v0.y;
                    C[nt][2] = v1.x; C[nt][3] = v1.y;
                }
            }
        }

        #pragma unroll
        for (int ks = 0; ks < 7; ks++) {
            const int aoff = row0 * (SKP / 2) + ks * 8 + t4;
            uint32_t ah[4], al[4];
            ah[0] = Ah32[aoff];
            ah[1] = Ah32[aoff + 4 * SKP];
            ah[2] = Ah32[aoff + 4];
            ah[3] = Ah32[aoff + 4 * SKP + 4];
            al[0] = Al32[aoff];
            al[1] = Al32[aoff + 4 * SKP];
            al[2] = Al32[aoff + 4];
            al[3] = Al32[aoff + 4 * SKP + 4];

            #pragma unroll
            for (int nt = 0; nt < 7; nt++) {
                if (nt < NT) {
                    const int boff = nbase + nt * 8 * (SKP / 2) + ks * 8;
                    uint32_t bh[2] = { Wh32[boff], Wh32[boff + 4] };
                    uint32_t bl[2] = { Wl32[boff], Wl32[boff + 4] };
                    mma16816(C[nt], ah, bh);
                    mma16816(C[nt], al, bh);
                    mma16816(C[nt], ah, bl);
                }
            }
        }

        #pragma unroll
        for (int nt = 0; nt < 7; nt++) {
            if (nt < NT) {
                const int u = (tstart + nt) * 2 + (t4 >> 1);
                #pragma unroll
                for (int r = 0; r < 2; r++) {
                    float p0 = C[nt][2 * r];
                    float p1 = C[nt][2 * r + 1];
                    float q0 = evn ? p0 : (p0 + p0);
                    float s  = sigm(q0);
                    float a0 = evn ? s : (s + s - 1.0f);       // even: i ; odd: g
                    float a1 = sigm(p1);                       // even: f ; odd: o
                    float pa0 = __shfl_xor_sync(0xFFFFFFFFu, a0, 1);
                    float pa1 = __shfl_xor_sync(0xFFFFFFFFu, a1, 1);
                    float iv = evn ? a0  : pa0;
                    float fv = evn ? a1  : pa1;
                    float gv = evn ? pa0 : a0;
                    float ov = evn ? pa1 : a1;
                    float cn = fmaf(fv, c[nt][r], iv * gv);
                    c[nt][r] = cn;
                    float sc = sigm(cn + cn);
                    float hv = ov * (sc + sc - 1.0f);

                    if (evn) {
                        int lrow = r ? row1 : row0;
                        __nv_bfloat16 hh = __float2bfloat16(hv);
                        float hl = hv - __bfloat162float(hh);
                        __nv_bfloat16 hlb = __float2bfloat16(hl);
                        AhW[lrow * SKP + u] = hh;
                        AlW[lrow * SKP + u] = hlb;
                        if (mode == 1) {
                            size_t off = ((size_t)(b0 + lrow) * TDIM + t) * 112 + u;
                            bool pos = hv > 0.0f;
                            g_hhi[off] = pos ? hh : zbf;
                            g_hlo[off] = pos ? hlb : zbf;
                        } else if (t == TDIM - 1) {
                            g_last[(b0 + lrow) * HDIM + u] = fmaxf(hv, 0.0f);
                        }
                    }
                }
            }
        }
        par ^= 1;
        __syncthreads();
    }
}

// ---------------- head: fc(8) + softmax ----------------
__global__ void head_kernel(const float* __restrict__ wfc,
                            const float* __restrict__ bfc,
                            float* __restrict__ out)
{
    int b = blockIdx.x * blockDim.x + threadIdx.x;
    if (b >= BDIM) return;
    const float* lr = g_last + b * HDIM;
    float lo[NCLS];
    #pragma unroll
    for (int cc = 0; cc < NCLS; cc++) {
        float s = bfc[cc];
        const float* wr = wfc + cc * HDIM;
        for (int u = 0; u < HDIM; u++) s = fmaf(lr[u], wr[u], s);
        lo[cc] = s;
    }
    float m = lo[0];
    #pragma unroll
    for (int cc = 1; cc < NCLS; cc++) m = fmaxf(m, lo[cc]);
    float sum = 0.0f;
    #pragma unroll
    for (int cc = 0; cc < NCLS; cc++) { lo[cc] = __expf(lo[cc] - m); sum += lo[cc]; }
    float inv = __fdividef(1.0f, sum);
    #pragma unroll
    for (int cc = 0; cc < NCLS; cc++) out[b * NCLS + cc] = lo[cc] * inv;
}

// ---------------- launch ----------------
extern "C" void kernel_launch(void* const* d_in, const int* in_sizes, int n_in,
                              void* d_out, int out_size)
{
    (void)in_sizes; (void)n_in; (void)out_size;
    const float* x     = (const float*)d_in[0];
    const float* w_ih1 = (const float*)d_in[1];
    const float* w_hh1 = (const float*)d_in[2];
    const float* b_ih1 = (const float*)d_in[3];
    const float* b_hh1 = (const float*)d_in[4];
    const float* w_ih2 = (const float*)d_in[5];
    const float* w_hh2 = (const float*)d_in[6];
    const float* b_ih2 = (const float*)d_in[7];
    const float* b_hh2 = (const float*)d_in[8];
    const float* w_fc  = (const float*)d_in[9];
    const float* b_fc  = (const float*)d_in[10];

    // smem: 1024 + 2*(208*SKPX*2) + 4*(128*SKPX*2)
    const int SZ64  = 1024 + 2 * (208 * 72  * 2) + 4 * (128 * 72  * 2);  // 134656
    const int SZ112 = 1024 + 2 * (208 * 120 * 2) + 4 * (128 * 120 * 2); // 223744
    const int SSC   = 2 * SWB + 4 * SAB;                                 // 222720

    cudaFuncSetAttribute((const void*)xproj_mma2<64, 72, 4>,
                         cudaFuncAttributeMaxDynamicSharedMemorySize, SZ64);
    cudaFuncSetAttribute((const void*)xproj_mma2<112, 120, 7>,
                         cudaFuncAttributeMaxDynamicSharedMemorySize, SZ112);
    cudaFuncSetAttribute((const void*)lstm_scan_mma,
                         cudaFuncAttributeMaxDynamicSharedMemorySize, SSC);

    void *xhi, *xlo, *hhi, *hlo;
    cudaGetSymbolAddress(&xhi, g_xhi);
    cudaGetSymbolAddress(&xlo, g_xlo);
    cudaGetSymbolAddress(&hhi, g_hhi);
    cudaGetSymbolAddress(&hlo, g_hlo);

    // prepass: x -> bf16 hi/lo; zero layer-2 pad columns
    prep_kernel<<<1024, 256>>>(x);
    // layer 1
    xproj_mma2<64, 72, 4><<<148, 256, SZ64>>>(
        (const __nv_bfloat16*)xhi, (const __nv_bfloat16*)xlo, w_ih1, 64, b_ih1, b_hh1);
    lstm_scan_mma<<<128, 512, SSC>>>(w_hh1, 1);
    // layer 2
    xproj_mma2<112, 120, 7><<<148, 256, SZ112>>>(
        (const __nv_bfloat16*)hhi, (const __nv_bfloat16*)hlo, w_ih2, 100, b_ih2, b_hh2);
    lstm_scan_mma<<<128, 512, SSC>>>(w_hh2, 2);
    // head
    head_kernel<<<(BDIM + 255) / 256, 256>>>(w_fc, b_fc, (float*)d_out);
}

// round 11
// speedup vs baseline: 1.0943x; 1.0943x over previous
#include <cuda_runtime.h>
#include <cuda_bf16.h>
#include <cstdint>
#include <cstddef>

// Problem dims
#define BDIM 4096
#define TDIM 128
#define DDIM 64
#define HDIM 100
#define G4   400          // 4*H
#define NCLS 8
#define M1   (BDIM * TDIM)   // 524288 rows

// ---------------- scratch (device globals; no allocation allowed) ----------
__device__ __align__(16) float g_xp[(size_t)M1 * G4];     // 800 MB, reused by both layers
__device__ __align__(16) float g_h1[(size_t)M1 * HDIM];   // relu(h) of layer 1 (fp32)
__device__ __align__(16) float g_last[BDIM * HDIM];       // relu(h_T) of layer 2
// bf16 hi/lo inputs for the two projection GEMMs
__device__ __align__(16) __nv_bfloat16 g_xhi[(size_t)M1 * 64];    // layer-1 x hi
__device__ __align__(16) __nv_bfloat16 g_xlo[(size_t)M1 * 64];    // layer-1 x lo
__device__ __align__(16) __nv_bfloat16 g_hhi[(size_t)M1 * 112];   // layer-2 in hi, K padded to 112
__device__ __align__(16) __nv_bfloat16 g_hlo[(size_t)M1 * 112];   // layer-2 in lo

// ---------------- helpers ----------------
__device__ __forceinline__ float sigm(float x) {
    return __fdividef(1.0f, 1.0f + __expf(-x));
}
__device__ __forceinline__ uint32_t pack_bf2(float a, float b) {
    __nv_bfloat162 p = __floats2bfloat162_rn(a, b);
    return *reinterpret_cast<uint32_t*>(&p);
}
__device__ __forceinline__ uint32_t smem_u32(const void* p) {
    uint32_t a;
    asm("{ .reg .u64 t; cvta.to.shared.u64 t, %1; cvt.u32.u64 %0, t; }" : "=r"(a) : "l"(p));
    return a;
}

// m16n8k16 row.col bf16 MMA with fp32 accumulate (HMMA on Blackwell)
__device__ __forceinline__ void mma16816(float c[4], const uint32_t a[4], const uint32_t b[2]) {
    asm volatile(
        "mma.sync.aligned.m16n8k16.row.col.f32.bf16.bf16.f32 "
        "{%0,%1,%2,%3}, {%4,%5,%6,%7}, {%8,%9}, {%0,%1,%2,%3};"
        : "+f"(c[0]), "+f"(c[1]), "+f"(c[2]), "+f"(c[3])
        : "r"(a[0]), "r"(a[1]), "r"(a[2]), "r"(a[3]), "r"(b[0]), "r"(b[1]));
}

#define LDSM_X4(r, addr) \
    asm volatile("ldmatrix.sync.aligned.m8n8.x4.shared.b16 {%0,%1,%2,%3}, [%4];" \
        : "=r"((r)[0]), "=r"((r)[1]), "=r"((r)[2]), "=r"((r)[3]) : "r"(addr))

__device__ __forceinline__ void cp16(uint32_t dst, const void* src) {
    asm volatile("cp.async.cg.shared.global [%0], [%1], 16;" :: "r"(dst), "l"(src));
}
#define CP_COMMIT() asm volatile("cp.async.commit_group;" ::: "memory")
#define CP_WAIT1()  asm volatile("cp.async.wait_group 1;" ::: "memory")

// ======================================================================
// Prepass 1: x fp32 -> g_xhi/g_xlo bf16
// ======================================================================
__global__ void prep_kernel(const float* __restrict__ x)
{
    const size_t stride = (size_t)gridDim.x * blockDim.x;
    const size_t gt = (size_t)blockIdx.x * blockDim.x + threadIdx.x;

    const size_t N4 = (size_t)M1 * 64 / 4;
    const float4* x4 = (const float4*)x;
    uint2* oh = (uint2*)g_xhi;
    uint2* ol = (uint2*)g_xlo;
    for (size_t i = gt; i < N4; i += stride) {
        float4 v = x4[i];
        float h0 = __bfloat162float(__float2bfloat16(v.x));
        float h1 = __bfloat162float(__float2bfloat16(v.y));
        float h2 = __bfloat162float(__float2bfloat16(v.z));
        float h3 = __bfloat162float(__float2bfloat16(v.w));
        oh[i] = make_uint2(pack_bf2(h0, h1), pack_bf2(h2, h3));
        ol[i] = make_uint2(pack_bf2(v.x - h0, v.y - h1), pack_bf2(v.z - h2, v.w - h3));
    }
}

// ======================================================================
// Prepass 2: g_h1 fp32 -> g_hhi/g_hlo bf16, pad cols 100..111 zero
// ======================================================================
__global__ void prep2_kernel()
{
    const size_t stride = (size_t)gridDim.x * blockDim.x;
    const size_t gt = (size_t)blockIdx.x * blockDim.x + threadIdx.x;
    const size_t NQ = (size_t)M1 * 28;     // 28 quads of 4 per 112-wide row

    uint2* oh = (uint2*)g_hhi;
    uint2* ol = (uint2*)g_hlo;
    for (size_t i = gt; i < NQ; i += stride) {
        size_t r = i / 28;
        int u0 = (int)(i - r * 28) * 4;
        float4 v;
        if (u0 < 100) v = *(const float4*)(g_h1 + r * HDIM + u0);
        else          v = make_float4(0.f, 0.f, 0.f, 0.f);
        float h0 = __bfloat162float(__float2bfloat16(v.x));
        float h1 = __bfloat162float(__float2bfloat16(v.y));
        float h2 = __bfloat162float(__float2bfloat16(v.z));
        float h3 = __bfloat162float(__float2bfloat16(v.w));
        size_t o = r * 28 + (size_t)(u0 >> 2);
        oh[o] = make_uint2(pack_bf2(h0, h1), pack_bf2(h2, h3));
        ol[o] = make_uint2(pack_bf2(v.x - h0, v.y - h1), pack_bf2(v.z - h2, v.w - h3));
    }
}

// ======================================================================
// Input-projection GEMM v3: g_xp = [Xhi+Xlo] @ W^T + (ba+bb)
// 512 threads = 16 warps = 8 m-tiles x 2 n-halves (13/12 n8-tiles per warp).
// cp.async double-buffered bf16 tiles, ldmatrix.x4 fragment loads.
// Gate-interleaved output (col' = unit*4 + gate); blockIdx&1 = gate half.
// ======================================================================
template <int KG, int SKPX, int KSTEPS>
__global__ __launch_bounds__(512) void xproj_mma2(
    const __nv_bfloat16* __restrict__ Xhi, const __nv_bfloat16* __restrict__ Xlo,
    const float* __restrict__ W, int Kw,
    const float* __restrict__ ba, const float* __restrict__ bb)
{
    constexpr int NH  = 200;
    constexpr int NWR = 208;                 // padded W rows (ldmatrix x4 overread)
    constexpr int WB  = NWR * SKPX * 2;
    constexpr int XB  = 128 * SKPX * 2;
    constexpr int NCH = KG / 8;              // 16B chunks per row

    extern __shared__ char sm[];
    float* bs = (float*)sm;                  // [200] bias
    char* WhiP = sm + 1024;

    const int tid  = threadIdx.x;
    const int wid  = tid >> 5;
    const int lane = tid & 31;
    const int g    = lane >> 2;
    const int t4   = lane & 3;
    const int hf   = blockIdx.x & 1;
    const int cta  = blockIdx.x >> 1;

    const uint32_t smb  = smem_u32(sm);
    const uint32_t wh_b = smb + 1024;
    const uint32_t wl_b = wh_b + (uint32_t)WB;
    const uint32_t x_b  = wh_b + 2u * (uint32_t)WB;

    // zero W buffers (covers K padding + row padding)
    {
        uint32_t* z = (uint32_t*)WhiP;
        for (int i = tid; i < 2 * WB / 4; i += 512) z[i] = 0;
    }
    __syncthreads();

    // convert W (hi/lo) + bias; smem slot n <-> W row gate*100 + (hf*50 + n/4)
    {
        const int KQ = Kw / 4;
        char* Whi = WhiP;
        char* Wlo = WhiP + WB;
        for (int i4 = tid; i4 < NH * KQ; i4 += 512) {
            int n = i4 / KQ, kq = i4 - n * KQ;
            int unit = hf * 50 + (n >> 2);
            int gate = n & 3;
            float4 v = *(const float4*)(W + (size_t)(gate * HDIM + unit) * Kw + kq * 4);
            float h0 = __bfloat162float(__float2bfloat16(v.x));
            float h1 = __bfloat162float(__float2bfloat16(v.y));
            float h2 = __bfloat162float(__float2bfloat16(v.z));
            float h3 = __bfloat162float(__float2bfloat16(v.w));
            uint32_t* ph = (uint32_t*)(Whi + (n * SKPX + kq * 4) * 2);
            uint32_t* pl = (uint32_t*)(Wlo + (n * SKPX + kq * 4) * 2);
            ph[0] = pack_bf2(h0, h1);
            ph[1] = pack_bf2(h2, h3);
            pl[0] = pack_bf2(v.x - h0, v.y - h1);
            pl[1] = pack_bf2(v.z - h2, v.w - h3);
        }
        for (int n = tid; n < NH; n += 512) {
            int wrow = (n & 3) * HDIM + hf * 50 + (n >> 2);
            bs[n] = ba[wrow] + bb[wrow];
        }
    }

    auto issue = [&](int tile, int p) {
        uint32_t dh = x_b + (uint32_t)p * (2u * XB);
        uint32_t dl = dh + (uint32_t)XB;
        const __nv_bfloat16* sh = Xhi + (size_t)tile * 128 * KG;
        const __nv_bfloat16* sl = Xlo + (size_t)tile * 128 * KG;
        for (int i = tid; i < 128 * NCH; i += 512) {
            int r = i / NCH, c = i - r * NCH;
            uint32_t doff = (uint32_t)(r * SKPX + c * 8) * 2;
            size_t soff = (size_t)r * KG + c * 8;
            cp16(dh + doff, sh + soff);
            cp16(dl + doff, sl + soff);
        }
    };

    issue(cta, 0);
    CP_COMMIT();

    const int mt   = wid & 7;          // m-tile (16 rows)
    const int nh2  = wid >> 3;         // n-half of the 200-col range
    const int m0   = mt * 16;
    const int NT   = nh2 ? 12 : 13;    // n8-tiles this warp owns
    const int NTP  = nh2 ? 6 : 7;      // x4 B-loads (2 tiles each)
    const int tbase = nh2 ? 13 : 0;

    const uint32_t a_off = (uint32_t)((m0 + (lane & 7) + ((lane >> 3) & 1) * 8) * SKPX * 2
                                      + ((lane >> 4) & 1) * 16);
    const uint32_t b_base = (uint32_t)((tbase * 8 + (lane & 7) + ((lane >> 4) & 1) * 8) * SKPX * 2
                                       + ((lane >> 3) & 1) * 16);

    int par = 0;
    for (int tile = cta; tile < 4096; tile += 74) {
        __syncthreads();                 // buf[par^1] free (previous compute done)
        int nt2 = tile + 74;
        if (nt2 < 4096) issue(nt2, par ^ 1);
        CP_COMMIT();
        CP_WAIT1();                      // buf[par] group complete (this thread)
        __syncthreads();                 // ... and for all threads

        float C[13][4];
        #pragma unroll
        for (int nt = 0; nt < 13; nt++)
            #pragma unroll
            for (int j = 0; j < 4; j++) C[nt][j] = 0.0f;

        const uint32_t axh = x_b + (uint32_t)par * (2u * XB) + a_off;
        const uint32_t axl = axh + (uint32_t)XB;

        #pragma unroll
        for (int ks = 0; ks < KSTEPS; ks++) {
            uint32_t ah[4], al[4];
            LDSM_X4(ah, axh + ks * 32);
            LDSM_X4(al, axl + ks * 32);
            #pragma unroll
            for (int ntp = 0; ntp < 7; ntp++) {
                if (ntp < NTP) {
                    uint32_t bh[4], bl[4];
                    uint32_t bo = b_base + (uint32_t)(ntp * 16 * SKPX * 2) + ks * 32;
                    LDSM_X4(bh, wh_b + bo);
                    LDSM_X4(bl, wl_b + bo);
                    mma16816(C[2 * ntp], ah, bh);
                    mma16816(C[2 * ntp], al, bh);
                    mma16816(C[2 * ntp], ah, bl);
                    if (2 * ntp + 1 < NT) {
                        mma16816(C[2 * ntp + 1], ah, bh + 2);
                        mma16816(C[2 * ntp + 1], al, bh + 2);
                        mma16816(C[2 * ntp + 1], ah, bl + 2);
                    }
                }
            }
        }

        // epilogue: add bias, store fp32
        float* out0 = g_xp + (size_t)(tile * 128 + m0 + g) * G4 + hf * NH;
        float* out1 = out0 + 8 * G4;
        #pragma unroll
        for (int nt = 0; nt < 13; nt++) {
            if (nt < NT) {
                int col = (tbase + nt) * 8 + t4 * 2;
                float2 b2 = *(float2*)(bs + col);
                *(float2*)(out0 + col) = make_float2(C[nt][0] + b2.x, C[nt][1] + b2.y);
                *(float2*)(out1 + col) = make_float2(C[nt][2] + b2.x, C[nt][3] + b2.y);
            }
        }
        par ^= 1;
    }
}

// ======================================================================
// Tensor-core recurrent scan (R8-proven structure and output path).
// mode 1: write relu(h) fp32 into g_h1.  mode 2: write relu(h_T) to g_last.
// ======================================================================
#define SKP 120                      // smem K stride (elements)
#define SWB (G4 * SKP * 2)           // 96000 B per W buffer
#define SAB (32 * SKP * 2)           // 7680 B per h buffer

__global__ __launch_bounds__(512) void lstm_scan_mma(
    const float* __restrict__ Whh, int mode)
{
    extern __shared__ char sm[];
    char* Whi   = sm;
    char* Wlo   = Whi + SWB;
    char* Abase = Wlo + SWB;         // 2 parity buffers x (hi, lo)

    const int tid  = threadIdx.x;
    const int wid  = tid >> 5;
    const int lane = tid & 31;
    const int g    = lane >> 2;
    const int t4   = lane & 3;
    const int b0   = blockIdx.x * 32;

    {
        uint32_t* z = (uint32_t*)sm;
        int tot = (2 * SWB + 4 * SAB) / 4;
        for (int i = tid; i < tot; i += 512) z[i] = 0;
    }
    __syncthreads();

    for (int i4 = tid; i4 < G4 * (HDIM / 4); i4 += 512) {
        int n = i4 / (HDIM / 4), kq = i4 - n * (HDIM / 4);
        int unit = n >> 2, gate = n & 3;
        float4 v = *(const float4*)(Whh + (size_t)(gate * HDIM + unit) * HDIM + kq * 4);
        float h0 = __bfloat162float(__float2bfloat16(v.x));
        float h1 = __bfloat162float(__float2bfloat16(v.y));
        float h2 = __bfloat162float(__float2bfloat16(v.z));
        float h3 = __bfloat162float(__float2bfloat16(v.w));
        uint32_t* ph = (uint32_t*)(Whi + (n * SKP + kq * 4) * 2);
        uint32_t* pl = (uint32_t*)(Wlo + (n * SKP + kq * 4) * 2);
        ph[0] = pack_bf2(h0, h1);
        ph[1] = pack_bf2(h2, h3);
        pl[0] = pack_bf2(v.x - h0, v.y - h1);
        pl[1] = pack_bf2(v.z - h2, v.w - h3);
    }
    __syncthreads();

    const uint32_t* Wh32 = (const uint32_t*)Whi;
    const uint32_t* Wl32 = (const uint32_t*)Wlo;

    const int mi     = wid & 1;
    const int ncol   = wid >> 1;                    // 0..7
    const int m0     = mi * 16;
    const int NT     = (ncol < 2) ? 7 : 6;
    const int tstart = (ncol < 2) ? ncol * 7 : 14 + (ncol - 2) * 6;
    const bool evn   = (t4 & 1) == 0;

    const int row0 = m0 + g;
    const int row1 = row0 + 8;

    float c[7][2];
    #pragma unroll
    for (int nt = 0; nt < 7; nt++) { c[nt][0] = 0.0f; c[nt][1] = 0.0f; }

    const int nbase = (tstart * 8 + g) * (SKP / 2) + t4;   // uint32 units

    int par = 0;
    for (int t = 0; t < TDIM; t++) {
        const uint32_t* Ah32 = (const uint32_t*)(Abase + par * (2 * SAB));
        const uint32_t* Al32 = Ah32 + SAB / 4;
        __nv_bfloat16* AhW = (__nv_bfloat16*)(Abase + (par ^ 1) * (2 * SAB));
        __nv_bfloat16* AlW = AhW + SAB / 2;

        float C[7][4];
        {
            const float* p0 = g_xp + ((size_t)(b0 + row0) * TDIM + t) * G4 + tstart * 8 + t4 * 2;
            const float* p1 = g_xp + ((size_t)(b0 + row1) * TDIM + t) * G4 + tstart * 8 + t4 * 2;
            #pragma unroll
            for (int nt = 0; nt < 7; nt++) {
                if (nt < NT) {
                    float2 v0 = *(const float2*)(p0 + nt * 8);
                    float2 v1 = *(const float2*)(p1 + nt * 8);
                    C[nt][0] = v0.x; C[nt][1] = v0.y;
                    C[nt][2] = v1.x; C[nt][3] = v1.y;
                }
            }
        }

        #pragma unroll
        for (int ks = 0; ks < 7; ks++) {
            const int aoff = row0 * (SKP / 2) + ks * 8 + t4;
            uint32_t ah[4], al[4];
            ah[0] = Ah32[aoff];
            ah[1] = Ah32[aoff + 4 * SKP];
            ah[2] = Ah32[aoff + 4];
            ah[3] = Ah32[aoff + 4 * SKP + 4];
            al[0] = Al32[aoff];
            al[1] = Al32[aoff + 4 * SKP];
            al[2] = Al32[aoff + 4];
            al[3] = Al32[aoff + 4 * SKP + 4];

            #pragma unroll
            for (int nt = 0; nt < 7; nt++) {
                if (nt < NT) {
                    const int boff = nbase + nt * 8 * (SKP / 2) + ks * 8;
                    uint32_t bh[2] = { Wh32[boff], Wh32[boff + 4] };
                    uint32_t bl[2] = { Wl32[boff], Wl32[boff + 4] };
                    mma16816(C[nt], ah, bh);
                    mma16816(C[nt], al, bh);
                    mma16816(C[nt], ah, bl);
                }
            }
        }

        #pragma unroll
        for (int nt = 0; nt < 7; nt++) {
            if (nt < NT) {
                const int u = (tstart + nt) * 2 + (t4 >> 1);
                #pragma unroll
                for (int r = 0; r < 2; r++) {
                    float p0 = C[nt][2 * r];
                    float p1 = C[nt][2 * r + 1];
                    float q0 = evn ? p0 : (p0 + p0);
                    float s  = sigm(q0);
                    float a0 = evn ? s : (s + s - 1.0f);       // even: i ; odd: g
                    float a1 = sigm(p1);                       // even: f ; odd: o
                    float pa0 = __shfl_xor_sync(0xFFFFFFFFu, a0, 1);
                    float pa1 = __shfl_xor_sync(0xFFFFFFFFu, a1, 1);
                    float iv = evn ? a0  : pa0;
                    float fv = evn ? a1  : pa1;
                    float gv = evn ? pa0 : a0;
                    float ov = evn ? pa1 : a1;
                    float cn = fmaf(fv, c[nt][r], iv * gv);
                    c[nt][r] = cn;
                    float sc = sigm(cn + cn);
                    float hv = ov * (sc + sc - 1.0f);

                    if (evn) {
                        int lrow = r ? row1 : row0;
                        __nv_bfloat16 hh = __float2bfloat16(hv);
                        float hl = hv - __bfloat162float(hh);
                        AhW[lrow * SKP + u] = hh;
                        AlW[lrow * SKP + u] = __float2bfloat16(hl);
                        if (mode == 1) {
                            g_h1[((size_t)(b0 + lrow) * TDIM + t) * HDIM + u] = fmaxf(hv, 0.0f);
                        } else if (t == TDIM - 1) {
                            g_last[(b0 + lrow) * HDIM + u] = fmaxf(hv, 0.0f);
                        }
                    }
                }
            }
        }
        par ^= 1;
        __syncthreads();
    }
}

// ---------------- head: fc(8) + softmax ----------------
__global__ void head_kernel(const float* __restrict__ wfc,
                            const float* __restrict__ bfc,
                            float* __restrict__ out)
{
    int b = blockIdx.x * blockDim.x + threadIdx.x;
    if (b >= BDIM) return;
    const float* lr = g_last + b * HDIM;
    float lo[NCLS];
    #pragma unroll
    for (int cc = 0; cc < NCLS; cc++) {
        float s = bfc[cc];
        const float* wr = wfc + cc * HDIM;
        for (int u = 0; u < HDIM; u++) s = fmaf(lr[u], wr[u], s);
        lo[cc] = s;
    }
    float m = lo[0];
    #pragma unroll
    for (int cc = 1; cc < NCLS; cc++) m = fmaxf(m, lo[cc]);
    float sum = 0.0f;
    #pragma unroll
    for (int cc = 0; cc < NCLS; cc++) { lo[cc] = __expf(lo[cc] - m); sum += lo[cc]; }
    float inv = __fdividef(1.0f, sum);
    #pragma unroll
    for (int cc = 0; cc < NCLS; cc++) out[b * NCLS + cc] = lo[cc] * inv;
}

// ---------------- launch ----------------
extern "C" void kernel_launch(void* const* d_in, const int* in_sizes, int n_in,
                              void* d_out, int out_size)
{
    (void)in_sizes; (void)n_in; (void)out_size;
    const float* x     = (const float*)d_in[0];
    const float* w_ih1 = (const float*)d_in[1];
    const float* w_hh1 = (const float*)d_in[2];
    const float* b_ih1 = (const float*)d_in[3];
    const float* b_hh1 = (const float*)d_in[4];
    const float* w_ih2 = (const float*)d_in[5];
    const float* w_hh2 = (const float*)d_in[6];
    const float* b_ih2 = (const float*)d_in[7];
    const float* b_hh2 = (const float*)d_in[8];
    const float* w_fc  = (const float*)d_in[9];
    const float* b_fc  = (const float*)d_in[10];

    // smem: 1024 + 2*(208*SKPX*2) + 4*(128*SKPX*2)
    const int SZ64  = 1024 + 2 * (208 * 72  * 2) + 4 * (128 * 72  * 2);  // 134656
    const int SZ112 = 1024 + 2 * (208 * 120 * 2) + 4 * (128 * 120 * 2); // 223744
    const int SSC   = 2 * SWB + 4 * SAB;                                 // 222720

    cudaFuncSetAttribute((const void*)xproj_mma2<64, 72, 4>,
                         cudaFuncAttributeMaxDynamicSharedMemorySize, SZ64);
    cudaFuncSetAttribute((const void*)xproj_mma2<112, 120, 7>,
                         cudaFuncAttributeMaxDynamicSharedMemorySize, SZ112);
    cudaFuncSetAttribute((const void*)lstm_scan_mma,
                         cudaFuncAttributeMaxDynamicSharedMemorySize, SSC);

    void *xhi, *xlo, *hhi, *hlo;
    cudaGetSymbolAddress(&xhi, g_xhi);
    cudaGetSymbolAddress(&xlo, g_xlo);
    cudaGetSymbolAddress(&hhi, g_hhi);
    cudaGetSymbolAddress(&hlo, g_hlo);

    // prepass: x -> bf16 hi/lo
    prep_kernel<<<1024, 256>>>(x);
    // layer 1
    xproj_mma2<64, 72, 4><<<148, 512, SZ64>>>(
        (const __nv_bfloat16*)xhi, (const __nv_bfloat16*)xlo, w_ih1, 64, b_ih1, b_hh1);
    lstm_scan_mma<<<128, 512, SSC>>>(w_hh1, 1);
    // between layers: h1 fp32 -> bf16 hi/lo (+pad)
    prep2_kernel<<<1024, 256>>>();
    // layer 2
    xproj_mma2<112, 120, 7><<<148, 512, SZ112>>>(
        (const __nv_bfloat16*)hhi, (const __nv_bfloat16*)hlo, w_ih2, 100, b_ih2, b_hh2);
    lstm_scan_mma<<<128, 512, SSC>>>(w_hh2, 2);
    // head
    head_kernel<<<(BDIM + 255) / 256, 256>>>(w_fc, b_fc, (float*)d_out);
}

// round 12
// speedup vs baseline: 1.1310x; 1.0336x over previous
#include <cuda_runtime.h>
#include <cuda_bf16.h>
#include <cstdint>
#include <cstddef>

// Problem dims
#define BDIM 4096
#define TDIM 128
#define DDIM 64
#define HDIM 100
#define G4   400          // 4*H
#define NCLS 8
#define M1   (BDIM * TDIM)   // 524288 rows

// ---------------- scratch (device globals; no allocation allowed) ----------
__device__ __align__(16) float g_xp[(size_t)M1 * G4];     // 800 MB, reused by both layers
__device__ __align__(16) float g_h1[(size_t)M1 * HDIM];   // relu(h) of layer 1 (fp32)
__device__ __align__(16) float g_last[BDIM * HDIM];       // relu(h_T) of layer 2
// bf16 hi/lo inputs for the two projection GEMMs
__device__ __align__(16) __nv_bfloat16 g_xhi[(size_t)M1 * 64];    // layer-1 x hi
__device__ __align__(16) __nv_bfloat16 g_xlo[(size_t)M1 * 64];    // layer-1 x lo
__device__ __align__(16) __nv_bfloat16 g_hhi[(size_t)M1 * 112];   // layer-2 in hi, K padded to 112
__device__ __align__(16) __nv_bfloat16 g_hlo[(size_t)M1 * 112];   // layer-2 in lo

// ---------------- helpers ----------------
__device__ __forceinline__ float sigm(float x) {
    return __fdividef(1.0f, 1.0f + __expf(-x));
}
__device__ __forceinline__ uint32_t pack_bf2(float a, float b) {
    __nv_bfloat162 p = __floats2bfloat162_rn(a, b);
    return *reinterpret_cast<uint32_t*>(&p);
}
__device__ __forceinline__ uint32_t smem_u32(const void* p) {
    uint32_t a;
    asm("{ .reg .u64 t; cvta.to.shared.u64 t, %1; cvt.u32.u64 %0, t; }" : "=r"(a) : "l"(p));
    return a;
}

// m16n8k16 row.col bf16 MMA with fp32 accumulate (HMMA on Blackwell)
__device__ __forceinline__ void mma16816(float c[4], const uint32_t a[4], const uint32_t b[2]) {
    asm volatile(
        "mma.sync.aligned.m16n8k16.row.col.f32.bf16.bf16.f32 "
        "{%0,%1,%2,%3}, {%4,%5,%6,%7}, {%8,%9}, {%0,%1,%2,%3};"
        : "+f"(c[0]), "+f"(c[1]), "+f"(c[2]), "+f"(c[3])
        : "r"(a[0]), "r"(a[1]), "r"(a[2]), "r"(a[3]), "r"(b[0]), "r"(b[1]));
}

#define LDSM_X4(r, addr) \
    asm volatile("ldmatrix.sync.aligned.m8n8.x4.shared.b16 {%0,%1,%2,%3}, [%4];" \
        : "=r"((r)[0]), "=r"((r)[1]), "=r"((r)[2]), "=r"((r)[3]) : "r"(addr))

__device__ __forceinline__ void cp16(uint32_t dst, const void* src) {
    asm volatile("cp.async.cg.shared.global [%0], [%1], 16;" :: "r"(dst), "l"(src));
}
#define CP_COMMIT() asm volatile("cp.async.commit_group;" ::: "memory")
#define CP_WAIT1()  asm volatile("cp.async.wait_group 1;" ::: "memory")

// ======================================================================
// Prepass 1: x fp32 -> g_xhi/g_xlo bf16
// ======================================================================
__global__ void prep_kernel(const float* __restrict__ x)
{
    const size_t stride = (size_t)gridDim.x * blockDim.x;
    const size_t gt = (size_t)blockIdx.x * blockDim.x + threadIdx.x;

    const size_t N4 = (size_t)M1 * 64 / 4;
    const float4* x4 = (const float4*)x;
    uint2* oh = (uint2*)g_xhi;
    uint2* ol = (uint2*)g_xlo;
    for (size_t i = gt; i < N4; i += stride) {
        float4 v = x4[i];
        float h0 = __bfloat162float(__float2bfloat16(v.x));
        float h1 = __bfloat162float(__float2bfloat16(v.y));
        float h2 = __bfloat162float(__float2bfloat16(v.z));
        float h3 = __bfloat162float(__float2bfloat16(v.w));
        oh[i] = make_uint2(pack_bf2(h0, h1), pack_bf2(h2, h3));
        ol[i] = make_uint2(pack_bf2(v.x - h0, v.y - h1), pack_bf2(v.z - h2, v.w - h3));
    }
}

// ======================================================================
// Prepass 2: g_h1 fp32 -> g_hhi/g_hlo bf16, pad cols 100..111 zero
// ======================================================================
__global__ void prep2_kernel()
{
    const size_t stride = (size_t)gridDim.x * blockDim.x;
    const size_t gt = (size_t)blockIdx.x * blockDim.x + threadIdx.x;
    const size_t NQ = (size_t)M1 * 28;     // 28 quads of 4 per 112-wide row

    uint2* oh = (uint2*)g_hhi;
    uint2* ol = (uint2*)g_hlo;
    for (size_t i = gt; i < NQ; i += stride) {
        size_t r = i / 28;
        int u0 = (int)(i - r * 28) * 4;
        float4 v;
        if (u0 < 100) v = *(const float4*)(g_h1 + r * HDIM + u0);
        else          v = make_float4(0.f, 0.f, 0.f, 0.f);
        float h0 = __bfloat162float(__float2bfloat16(v.x));
        float h1 = __bfloat162float(__float2bfloat16(v.y));
        float h2 = __bfloat162float(__float2bfloat16(v.z));
        float h3 = __bfloat162float(__float2bfloat16(v.w));
        size_t o = r * 28 + (size_t)(u0 >> 2);
        oh[o] = make_uint2(pack_bf2(h0, h1), pack_bf2(h2, h3));
        ol[o] = make_uint2(pack_bf2(v.x - h0, v.y - h1), pack_bf2(v.z - h2, v.w - h3));
    }
}

// ======================================================================
// Input-projection GEMM (R10-measured 256-thread config, 456us @ K=112):
// g_xp = [Xhi+Xlo] @ W^T + (ba+bb); cp.async double-buffered, ldmatrix.x4.
// Gate-interleaved output (col' = unit*4 + gate); blockIdx&1 = gate half.
// ======================================================================
template <int KG, int SKPX, int KSTEPS>
__global__ __launch_bounds__(256) void xproj_mma2(
    const __nv_bfloat16* __restrict__ Xhi, const __nv_bfloat16* __restrict__ Xlo,
    const float* __restrict__ W, int Kw,
    const float* __restrict__ ba, const float* __restrict__ bb)
{
    constexpr int NH  = 200;
    constexpr int NWR = 208;                 // padded W rows (ldmatrix x4 overread)
    constexpr int WB  = NWR * SKPX * 2;
    constexpr int XB  = 128 * SKPX * 2;
    constexpr int NCH = KG / 8;              // 16B chunks per row

    extern __shared__ char sm[];
    float* bs = (float*)sm;                  // [200] bias
    char* WhiP = sm + 1024;

    const int tid  = threadIdx.x;
    const int wid  = tid >> 5;
    const int lane = tid & 31;
    const int g    = lane >> 2;
    const int t4   = lane & 3;
    const int hf   = blockIdx.x & 1;
    const int cta  = blockIdx.x >> 1;

    const uint32_t smb  = smem_u32(sm);
    const uint32_t wh_b = smb + 1024;
    const uint32_t wl_b = wh_b + (uint32_t)WB;
    const uint32_t x_b  = wh_b + 2u * (uint32_t)WB;

    // zero W buffers (covers K padding + row padding)
    {
        uint32_t* z = (uint32_t*)WhiP;
        for (int i = tid; i < 2 * WB / 4; i += 256) z[i] = 0;
    }
    __syncthreads();

    // convert W (hi/lo) + bias; smem slot n <-> W row gate*100 + (hf*50 + n/4)
    {
        const int KQ = Kw / 4;
        char* Whi = WhiP;
        char* Wlo = WhiP + WB;
        for (int i4 = tid; i4 < NH * KQ; i4 += 256) {
            int n = i4 / KQ, kq = i4 - n * KQ;
            int unit = hf * 50 + (n >> 2);
            int gate = n & 3;
            float4 v = *(const float4*)(W + (size_t)(gate * HDIM + unit) * Kw + kq * 4);
            float h0 = __bfloat162float(__float2bfloat16(v.x));
            float h1 = __bfloat162float(__float2bfloat16(v.y));
            float h2 = __bfloat162float(__float2bfloat16(v.z));
            float h3 = __bfloat162float(__float2bfloat16(v.w));
            uint32_t* ph = (uint32_t*)(Whi + (n * SKPX + kq * 4) * 2);
            uint32_t* pl = (uint32_t*)(Wlo + (n * SKPX + kq * 4) * 2);
            ph[0] = pack_bf2(h0, h1);
            ph[1] = pack_bf2(h2, h3);
            pl[0] = pack_bf2(v.x - h0, v.y - h1);
            pl[1] = pack_bf2(v.z - h2, v.w - h3);
        }
        for (int n = tid; n < NH; n += 256) {
            int wrow = (n & 3) * HDIM + hf * 50 + (n >> 2);
            bs[n] = ba[wrow] + bb[wrow];
        }
    }

    auto issue = [&](int tile, int p) {
        uint32_t dh = x_b + (uint32_t)p * (2u * XB);
        uint32_t dl = dh + (uint32_t)XB;
        const __nv_bfloat16* sh = Xhi + (size_t)tile * 128 * KG;
        const __nv_bfloat16* sl = Xlo + (size_t)tile * 128 * KG;
        for (int i = tid; i < 128 * NCH; i += 256) {
            int r = i / NCH, c = i - r * NCH;
            uint32_t doff = (uint32_t)(r * SKPX + c * 8) * 2;
            size_t soff = (size_t)r * KG + c * 8;
            cp16(dh + doff, sh + soff);
            cp16(dl + doff, sl + soff);
        }
    };

    issue(cta, 0);
    CP_COMMIT();

    const int m0 = wid * 16;
    const uint32_t a_off = (uint32_t)((m0 + (lane & 7) + ((lane >> 3) & 1) * 8) * SKPX * 2
                                      + ((lane >> 4) & 1) * 16);
    const uint32_t b_off = (uint32_t)(((lane & 7) + ((lane >> 4) & 1) * 8) * SKPX * 2
                                      + ((lane >> 3) & 1) * 16);

    int par = 0;
    for (int tile = cta; tile < 4096; tile += 74) {
        __syncthreads();                 // buf[par^1] free (previous compute done)
        int nt2 = tile + 74;
        if (nt2 < 4096) issue(nt2, par ^ 1);
        CP_COMMIT();
        CP_WAIT1();                      // buf[par] group complete (this thread)
        __syncthreads();                 // ... and for all threads

        float C[25][4];
        #pragma unroll
        for (int nt = 0; nt < 25; nt++)
            #pragma unroll
            for (int j = 0; j < 4; j++) C[nt][j] = 0.0f;

        const uint32_t axh = x_b + (uint32_t)par * (2u * XB) + a_off;
        const uint32_t axl = axh + (uint32_t)XB;

        #pragma unroll
        for (int ks = 0; ks < KSTEPS; ks++) {
            uint32_t ah[4], al[4];
            LDSM_X4(ah, axh + ks * 32);
            LDSM_X4(al, axl + ks * 32);
            #pragma unroll
            for (int ntp = 0; ntp < 13; ntp++) {
                uint32_t bh[4], bl[4];
                uint32_t bo = b_off + (uint32_t)(ntp * 16 * SKPX * 2) + ks * 32;
                LDSM_X4(bh, wh_b + bo);
                LDSM_X4(bl, wl_b + bo);
                mma16816(C[2 * ntp], ah, bh);
                mma16816(C[2 * ntp], al, bh);
                mma16816(C[2 * ntp], ah, bl);
                if (2 * ntp + 1 < 25) {
                    mma16816(C[2 * ntp + 1], ah, bh + 2);
                    mma16816(C[2 * ntp + 1], al, bh + 2);
                    mma16816(C[2 * ntp + 1], ah, bl + 2);
                }
            }
        }

        // epilogue: add bias, store fp32
        float* out0 = g_xp + (size_t)(tile * 128 + m0 + g) * G4 + hf * NH;
        float* out1 = out0 + 8 * G4;
        #pragma unroll
        for (int nt = 0; nt < 25; nt++) {
            int col = nt * 8 + t4 * 2;
            float2 b2 = *(float2*)(bs + col);
            *(float2*)(out0 + col) = make_float2(C[nt][0] + b2.x, C[nt][1] + b2.y);
            *(float2*)(out1 + col) = make_float2(C[nt][2] + b2.x, C[nt][3] + b2.y);
        }
        par ^= 1;
    }
}

// ======================================================================
// Tensor-core recurrent scan v3: ldmatrix.x4 fragment loads.
// 128 blocks x 32 batch rows, 512 threads (16 warps = 2 m-tiles x 8 n-cols).
// Whh smem bf16 hi/lo gate-interleaved (row n' = unit*4+gate, stride 120).
// h state double-buffered bf16 hi/lo; ONE barrier per step.
// mode 1: write relu(h) fp32 into g_h1.  mode 2: write relu(h_T) to g_last.
// ======================================================================
#define SKP 120                      // smem K stride (elements)
#define SWB (G4 * SKP * 2)           // 96000 B per W buffer
#define SAB (32 * SKP * 2)           // 7680 B per h buffer

__global__ __launch_bounds__(512) void lstm_scan_mma(
    const float* __restrict__ Whh, int mode)
{
    extern __shared__ char sm[];
    char* Whi   = sm;
    char* Wlo   = Whi + SWB;
    char* Abase = Wlo + SWB;         // 2 parity buffers x (hi, lo)

    const int tid  = threadIdx.x;
    const int wid  = tid >> 5;
    const int lane = tid & 31;
    const int g    = lane >> 2;
    const int t4   = lane & 3;
    const int b0   = blockIdx.x * 32;

    {
        uint32_t* z = (uint32_t*)sm;
        int tot = (2 * SWB + 4 * SAB) / 4;
        for (int i = tid; i < tot; i += 512) z[i] = 0;
    }
    __syncthreads();

    for (int i4 = tid; i4 < G4 * (HDIM / 4); i4 += 512) {
        int n = i4 / (HDIM / 4), kq = i4 - n * (HDIM / 4);
        int unit = n >> 2, gate = n & 3;
        float4 v = *(const float4*)(Whh + (size_t)(gate * HDIM + unit) * HDIM + kq * 4);
        float h0 = __bfloat162float(__float2bfloat16(v.x));
        float h1 = __bfloat162float(__float2bfloat16(v.y));
        float h2 = __bfloat162float(__float2bfloat16(v.z));
        float h3 = __bfloat162float(__float2bfloat16(v.w));
        uint32_t* ph = (uint32_t*)(Whi + (n * SKP + kq * 4) * 2);
        uint32_t* pl = (uint32_t*)(Wlo + (n * SKP + kq * 4) * 2);
        ph[0] = pack_bf2(h0, h1);
        ph[1] = pack_bf2(h2, h3);
        pl[0] = pack_bf2(v.x - h0, v.y - h1);
        pl[1] = pack_bf2(v.z - h2, v.w - h3);
    }
    __syncthreads();

    const uint32_t smb  = smem_u32(sm);
    const uint32_t wh_b = smb;
    const uint32_t wl_b = smb + (uint32_t)SWB;
    const uint32_t a_b  = smb + 2u * (uint32_t)SWB;

    const int mi     = wid & 1;
    const int ncol   = wid >> 1;                    // 0..7
    const int m0     = mi * 16;
    const int NT     = (ncol < 2) ? 7 : 6;
    const int tstart = (ncol < 2) ? ncol * 7 : 14 + (ncol - 2) * 6;
    const bool evn   = (t4 & 1) == 0;

    const int row0 = m0 + g;
    const int row1 = row0 + 8;

    float c[7][2];
    #pragma unroll
    for (int nt = 0; nt < 7; nt++) { c[nt][0] = 0.0f; c[nt][1] = 0.0f; }

    // ldmatrix fragment addresses
    const uint32_t a_off = (uint32_t)((m0 + (lane & 7) + ((lane >> 3) & 1) * 8) * SKP * 2
                                      + ((lane >> 4) & 1) * 16);
    const uint32_t b_base = (uint32_t)((tstart * 8 + (lane & 7) + ((lane >> 4) & 1) * 8) * SKP * 2
                                       + ((lane >> 3) & 1) * 16);

    int par = 0;
    for (int t = 0; t < TDIM; t++) {
        __nv_bfloat16* AhW = (__nv_bfloat16*)(Abase + (par ^ 1) * (2 * SAB));
        __nv_bfloat16* AlW = AhW + SAB / 2;

        // accumulators initialized from x-projection (gate-interleaved, coalesced)
        float C[7][4];
        {
            const float* p0 = g_xp + ((size_t)(b0 + row0) * TDIM + t) * G4 + tstart * 8 + t4 * 2;
            const float* p1 = g_xp + ((size_t)(b0 + row1) * TDIM + t) * G4 + tstart * 8 + t4 * 2;
            #pragma unroll
            for (int nt = 0; nt < 7; nt++) {
                if (nt < NT) {
                    float2 v0 = *(const float2*)(p0 + nt * 8);
                    float2 v1 = *(const float2*)(p1 + nt * 8);
                    C[nt][0] = v0.x; C[nt][1] = v0.y;
                    C[nt][2] = v1.x; C[nt][3] = v1.y;
                }
            }
        }

        const uint32_t axh = a_b + (uint32_t)par * (2u * SAB) + a_off;
        const uint32_t axl = axh + (uint32_t)SAB;

        #pragma unroll
        for (int ks = 0; ks < 7; ks++) {
            uint32_t ah[4], al[4];
            LDSM_X4(ah, axh + ks * 32);
            LDSM_X4(al, axl + ks * 32);
            #pragma unroll
            for (int p = 0; p < 4; p++) {
                if (2 * p < NT) {
                    uint32_t bh[4], bl[4];
                    uint32_t bo = b_base + (uint32_t)(p * 16 * SKP * 2) + ks * 32;
                    LDSM_X4(bh, wh_b + bo);
                    LDSM_X4(bl, wl_b + bo);
                    mma16816(C[2 * p], ah, bh);
                    mma16816(C[2 * p], al, bh);
                    mma16816(C[2 * p], ah, bl);
                    if (2 * p + 1 < NT) {
                        mma16816(C[2 * p + 1], ah, bh + 2);
                        mma16816(C[2 * p + 1], al, bh + 2);
                        mma16816(C[2 * p + 1], ah, bl + 2);
                    }
                }
            }
        }

        // gates -> c,h.  Lane pairs: even t4 holds (i,f), odd holds (g,o).
        #pragma unroll
        for (int nt = 0; nt < 7; nt++) {
            if (nt < NT) {
                const int u = (tstart + nt) * 2 + (t4 >> 1);
                #pragma unroll
                for (int r = 0; r < 2; r++) {
                    float p0 = C[nt][2 * r];
                    float p1 = C[nt][2 * r + 1];
                    float q0 = evn ? p0 : (p0 + p0);
                    float s  = sigm(q0);
                    float a0 = evn ? s : (s + s - 1.0f);       // even: i ; odd: g
                    float a1 = sigm(p1);                       // even: f ; odd: o
                    float pa0 = __shfl_xor_sync(0xFFFFFFFFu, a0, 1);
                    float pa1 = __shfl_xor_sync(0xFFFFFFFFu, a1, 1);
                    float iv = evn ? a0  : pa0;
                    float fv = evn ? a1  : pa1;
                    float gv = evn ? pa0 : a0;
                    float ov = evn ? pa1 : a1;
                    float cn = fmaf(fv, c[nt][r], iv * gv);
                    c[nt][r] = cn;
                    float sc = sigm(cn + cn);
                    float hv = ov * (sc + sc - 1.0f);

                    if (evn) {
                        int lrow = r ? row1 : row0;
                        __nv_bfloat16 hh = __float2bfloat16(hv);
                        float hl = hv - __bfloat162float(hh);
                        AhW[lrow * SKP + u] = hh;
                        AlW[lrow * SKP + u] = __float2bfloat16(hl);
                        if (mode == 1) {
                            g_h1[((size_t)(b0 + lrow) * TDIM + t) * HDIM + u] = fmaxf(hv, 0.0f);
                        } else if (t == TDIM - 1) {
                            g_last[(b0 + lrow) * HDIM + u] = fmaxf(hv, 0.0f);
                        }
                    }
                }
            }
        }
        par ^= 1;
        __syncthreads();   // h(t) visible before next step's reads
    }
}

// ---------------- head: fc(8) + softmax ----------------
__global__ void head_kernel(const float* __restrict__ wfc,
                            const float* __restrict__ bfc,
                            float* __restrict__ out)
{
    int b = blockIdx.x * blockDim.x + threadIdx.x;
    if (b >= BDIM) return;
    const float* lr = g_last + b * HDIM;
    float lo[NCLS];
    #pragma unroll
    for (int cc = 0; cc < NCLS; cc++) {
        float s = bfc[cc];
        const float* wr = wfc + cc * HDIM;
        for (int u = 0; u < HDIM; u++) s = fmaf(lr[u], wr[u], s);
        lo[cc] = s;
    }
    float m = lo[0];
    #pragma unroll
    for (int cc = 1; cc < NCLS; cc++) m = fmaxf(m, lo[cc]);
    float sum = 0.0f;
    #pragma unroll
    for (int cc = 0; cc < NCLS; cc++) { lo[cc] = __expf(lo[cc] - m); sum += lo[cc]; }
    float inv = __fdividef(1.0f, sum);
    #pragma unroll
    for (int cc = 0; cc < NCLS; cc++) out[b * NCLS + cc] = lo[cc] * inv;
}

// ---------------- launch ----------------
extern "C" void kernel_launch(void* const* d_in, const int* in_sizes, int n_in,
                              void* d_out, int out_size)
{
    (void)in_sizes; (void)n_in; (void)out_size;
    const float* x     = (const float*)d_in[0];
    const float* w_ih1 = (const float*)d_in[1];
    const float* w_hh1 = (const float*)d_in[2];
    const float* b_ih1 = (const float*)d_in[3];
    const float* b_hh1 = (const float*)d_in[4];
    const float* w_ih2 = (const float*)d_in[5];
    const float* w_hh2 = (const float*)d_in[6];
    const float* b_ih2 = (const float*)d_in[7];
    const float* b_hh2 = (const float*)d_in[8];
    const float* w_fc  = (const float*)d_in[9];
    const float* b_fc  = (const float*)d_in[10];

    // smem: 1024 + 2*(208*SKPX*2) + 4*(128*SKPX*2)
    const int SZ64  = 1024 + 2 * (208 * 72  * 2) + 4 * (128 * 72  * 2);  // 134656
    const int SZ112 = 1024 + 2 * (208 * 120 * 2) + 4 * (128 * 120 * 2); // 223744
    const int SSC   = 2 * SWB + 4 * SAB;                                 // 222720

    cudaFuncSetAttribute((const void*)xproj_mma2<64, 72, 4>,
                         cudaFuncAttributeMaxDynamicSharedMemorySize, SZ64);
    cudaFuncSetAttribute((const void*)xproj_mma2<112, 120, 7>,
                         cudaFuncAttributeMaxDynamicSharedMemorySize, SZ112);
    cudaFuncSetAttribute((const void*)lstm_scan_mma,
                         cudaFuncAttributeMaxDynamicSharedMemorySize, SSC);

    void *xhi, *xlo, *hhi, *hlo;
    cudaGetSymbolAddress(&xhi, g_xhi);
    cudaGetSymbolAddress(&xlo, g_xlo);
    cudaGetSymbolAddress(&hhi, g_hhi);
    cudaGetSymbolAddress(&hlo, g_hlo);

    // prepass: x -> bf16 hi/lo
    prep_kernel<<<1024, 256>>>(x);
    // layer 1
    xproj_mma2<64, 72, 4><<<148, 256, SZ64>>>(
        (const __nv_bfloat16*)xhi, (const __nv_bfloat16*)xlo, w_ih1, 64, b_ih1, b_hh1);
    lstm_scan_mma<<<128, 512, SSC>>>(w_hh1, 1);
    // between layers: h1 fp32 -> bf16 hi/lo (+pad)
    prep2_kernel<<<1024, 256>>>();
    // layer 2
    xproj_mma2<112, 120, 7><<<148, 256, SZ112>>>(
        (const __nv_bfloat16*)hhi, (const __nv_bfloat16*)hlo, w_ih2, 100, b_ih2, b_hh2);
    lstm_scan_mma<<<128, 512, SSC>>>(w_hh2, 2);
    // head
    head_kernel<<<(BDIM + 255) / 256, 256>>>(w_fc, b_fc, (float*)d_out);
}

// round 13
// speedup vs baseline: 1.3991x; 1.2371x over previous
#include <cuda_runtime.h>
#include <cuda_bf16.h>
#include <cstdint>
#include <cstddef>

// Problem dims
#define BDIM 4096
#define TDIM 128
#define DDIM 64
#define HDIM 100
#define G4   400          // 4*H
#define NCLS 8
#define M1   (BDIM * TDIM)   // 524288 rows

// ---------------- scratch (device globals; no allocation allowed) ----------
__device__ __align__(16) float g_xp[(size_t)M1 * G4];     // 800 MB, reused by both layers
__device__ __align__(16) float g_h1[(size_t)M1 * HDIM];   // relu(h) of layer 1 (fp32)
__device__ __align__(16) float g_last[BDIM * HDIM];       // relu(h_T) of layer 2
// bf16 hi/lo inputs for the two projection GEMMs
__device__ __align__(16) __nv_bfloat16 g_xhi[(size_t)M1 * 64];    // layer-1 x hi
__device__ __align__(16) __nv_bfloat16 g_xlo[(size_t)M1 * 64];    // layer-1 x lo
__device__ __align__(16) __nv_bfloat16 g_hhi[(size_t)M1 * 112];   // layer-2 in hi, K padded to 112
__device__ __align__(16) __nv_bfloat16 g_hlo[(size_t)M1 * 112];   // layer-2 in lo

// ---------------- helpers ----------------
__device__ __forceinline__ float sigm(float x) {
    return __fdividef(1.0f, 1.0f + __expf(-x));
}
__device__ __forceinline__ uint32_t pack_bf2(float a, float b) {
    __nv_bfloat162 p = __floats2bfloat162_rn(a, b);
    return *reinterpret_cast<uint32_t*>(&p);
}
__device__ __forceinline__ uint32_t smem_u32(const void* p) {
    uint32_t a;
    asm("{ .reg .u64 t; cvta.to.shared.u64 t, %1; cvt.u32.u64 %0, t; }" : "=r"(a) : "l"(p));
    return a;
}

// m16n8k16 row.col bf16 MMA with fp32 accumulate (HMMA on Blackwell)
__device__ __forceinline__ void mma16816(float c[4], const uint32_t a[4], const uint32_t b[2]) {
    asm volatile(
        "mma.sync.aligned.m16n8k16.row.col.f32.bf16.bf16.f32 "
        "{%0,%1,%2,%3}, {%4,%5,%6,%7}, {%8,%9}, {%0,%1,%2,%3};"
        : "+f"(c[0]), "+f"(c[1]), "+f"(c[2]), "+f"(c[3])
        : "r"(a[0]), "r"(a[1]), "r"(a[2]), "r"(a[3]), "r"(b[0]), "r"(b[1]));
}

#define LDSM_X4(r, addr) \
    asm volatile("ldmatrix.sync.aligned.m8n8.x4.shared.b16 {%0,%1,%2,%3}, [%4];" \
        : "=r"((r)[0]), "=r"((r)[1]), "=r"((r)[2]), "=r"((r)[3]) : "r"(addr))

__device__ __forceinline__ void cp16(uint32_t dst, const void* src) {
    asm volatile("cp.async.cg.shared.global [%0], [%1], 16;" :: "r"(dst), "l"(src));
}
#define CP_COMMIT() asm volatile("cp.async.commit_group;" ::: "memory")
#define CP_WAIT1()  asm volatile("cp.async.wait_group 1;" ::: "memory")

// ======================================================================
// Prepass 1: x fp32 -> g_xhi/g_xlo bf16
// ======================================================================
__global__ void prep_kernel(const float* __restrict__ x)
{
    const size_t stride = (size_t)gridDim.x * blockDim.x;
    const size_t gt = (size_t)blockIdx.x * blockDim.x + threadIdx.x;

    const size_t N4 = (size_t)M1 * 64 / 4;
    const float4* x4 = (const float4*)x;
    uint2* oh = (uint2*)g_xhi;
    uint2* ol = (uint2*)g_xlo;
    for (size_t i = gt; i < N4; i += stride) {
        float4 v = x4[i];
        float h0 = __bfloat162float(__float2bfloat16(v.x));
        float h1 = __bfloat162float(__float2bfloat16(v.y));
        float h2 = __bfloat162float(__float2bfloat16(v.z));
        float h3 = __bfloat162float(__float2bfloat16(v.w));
        oh[i] = make_uint2(pack_bf2(h0, h1), pack_bf2(h2, h3));
        ol[i] = make_uint2(pack_bf2(v.x - h0, v.y - h1), pack_bf2(v.z - h2, v.w - h3));
    }
}

// ======================================================================
// Prepass 2: g_h1 fp32 -> g_hhi/g_hlo bf16, pad cols 100..111 zero
// ======================================================================
__global__ void prep2_kernel()
{
    const size_t stride = (size_t)gridDim.x * blockDim.x;
    const size_t gt = (size_t)blockIdx.x * blockDim.x + threadIdx.x;
    const size_t NQ = (size_t)M1 * 28;     // 28 quads of 4 per 112-wide row

    uint2* oh = (uint2*)g_hhi;
    uint2* ol = (uint2*)g_hlo;
    for (size_t i = gt; i < NQ; i += stride) {
        size_t r = i / 28;
        int u0 = (int)(i - r * 28) * 4;
        float4 v;
        if (u0 < 100) v = *(const float4*)(g_h1 + r * HDIM + u0);
        else          v = make_float4(0.f, 0.f, 0.f, 0.f);
        float h0 = __bfloat162float(__float2bfloat16(v.x));
        float h1 = __bfloat162float(__float2bfloat16(v.y));
        float h2 = __bfloat162float(__float2bfloat16(v.z));
        float h3 = __bfloat162float(__float2bfloat16(v.w));
        size_t o = r * 28 + (size_t)(u0 >> 2);
        oh[o] = make_uint2(pack_bf2(h0, h1), pack_bf2(h2, h3));
        ol[o] = make_uint2(pack_bf2(v.x - h0, v.y - h1), pack_bf2(v.z - h2, v.w - h3));
    }
}

// ======================================================================
// Input-projection GEMM (R10-measured 256-thread config):
// g_xp = [Xhi+Xlo] @ W^T + (ba+bb); cp.async double-buffered, ldmatrix.x4.
// Gate-interleaved output (col' = unit*4 + gate); blockIdx&1 = gate half.
// 3-term bf16 split (kept: xproj feeds everything, precision preserved).
// ======================================================================
template <int KG, int SKPX, int KSTEPS>
__global__ __launch_bounds__(256) void xproj_mma2(
    const __nv_bfloat16* __restrict__ Xhi, const __nv_bfloat16* __restrict__ Xlo,
    const float* __restrict__ W, int Kw,
    const float* __restrict__ ba, const float* __restrict__ bb)
{
    constexpr int NH  = 200;
    constexpr int NWR = 208;                 // padded W rows (ldmatrix x4 overread)
    constexpr int WB  = NWR * SKPX * 2;
    constexpr int XB  = 128 * SKPX * 2;
    constexpr int NCH = KG / 8;              // 16B chunks per row

    extern __shared__ char sm[];
    float* bs = (float*)sm;                  // [200] bias
    char* WhiP = sm + 1024;

    const int tid  = threadIdx.x;
    const int wid  = tid >> 5;
    const int lane = tid & 31;
    const int g    = lane >> 2;
    const int t4   = lane & 3;
    const int hf   = blockIdx.x & 1;
    const int cta  = blockIdx.x >> 1;

    const uint32_t smb  = smem_u32(sm);
    const uint32_t wh_b = smb + 1024;
    const uint32_t wl_b = wh_b + (uint32_t)WB;
    const uint32_t x_b  = wh_b + 2u * (uint32_t)WB;

    // zero W buffers (covers K padding + row padding)
    {
        uint32_t* z = (uint32_t*)WhiP;
        for (int i = tid; i < 2 * WB / 4; i += 256) z[i] = 0;
    }
    __syncthreads();

    // convert W (hi/lo) + bias; smem slot n <-> W row gate*100 + (hf*50 + n/4)
    {
        const int KQ = Kw / 4;
        char* Whi = WhiP;
        char* Wlo = WhiP + WB;
        for (int i4 = tid; i4 < NH * KQ; i4 += 256) {
            int n = i4 / KQ, kq = i4 - n * KQ;
            int unit = hf * 50 + (n >> 2);
            int gate = n & 3;
            float4 v = *(const float4*)(W + (size_t)(gate * HDIM + unit) * Kw + kq * 4);
            float h0 = __bfloat162float(__float2bfloat16(v.x));
            float h1 = __bfloat162float(__float2bfloat16(v.y));
            float h2 = __bfloat162float(__float2bfloat16(v.z));
            float h3 = __bfloat162float(__float2bfloat16(v.w));
            uint32_t* ph = (uint32_t*)(Whi + (n * SKPX + kq * 4) * 2);
            uint32_t* pl = (uint32_t*)(Wlo + (n * SKPX + kq * 4) * 2);
            ph[0] = pack_bf2(h0, h1);
            ph[1] = pack_bf2(h2, h3);
            pl[0] = pack_bf2(v.x - h0, v.y - h1);
            pl[1] = pack_bf2(v.z - h2, v.w - h3);
        }
        for (int n = tid; n < NH; n += 256) {
            int wrow = (n & 3) * HDIM + hf * 50 + (n >> 2);
            bs[n] = ba[wrow] + bb[wrow];
        }
    }

    auto issue = [&](int tile, int p) {
        uint32_t dh = x_b + (uint32_t)p * (2u * XB);
        uint32_t dl = dh + (uint32_t)XB;
        const __nv_bfloat16* sh = Xhi + (size_t)tile * 128 * KG;
        const __nv_bfloat16* sl = Xlo + (size_t)tile * 128 * KG;
        for (int i = tid; i < 128 * NCH; i += 256) {
            int r = i / NCH, c = i - r * NCH;
            uint32_t doff = (uint32_t)(r * SKPX + c * 8) * 2;
            size_t soff = (size_t)r * KG + c * 8;
            cp16(dh + doff, sh + soff);
            cp16(dl + doff, sl + soff);
        }
    };

    issue(cta, 0);
    CP_COMMIT();

    const int m0 = wid * 16;
    const uint32_t a_off = (uint32_t)((m0 + (lane & 7) + ((lane >> 3) & 1) * 8) * SKPX * 2
                                      + ((lane >> 4) & 1) * 16);
    const uint32_t b_off = (uint32_t)(((lane & 7) + ((lane >> 4) & 1) * 8) * SKPX * 2
                                      + ((lane >> 3) & 1) * 16);

    int par = 0;
    for (int tile = cta; tile < 4096; tile += 74) {
        __syncthreads();                 // buf[par^1] free (previous compute done)
        int nt2 = tile + 74;
        if (nt2 < 4096) issue(nt2, par ^ 1);
        CP_COMMIT();
        CP_WAIT1();                      // buf[par] group complete (this thread)
        __syncthreads();                 // ... and for all threads

        float C[25][4];
        #pragma unroll
        for (int nt = 0; nt < 25; nt++)
            #pragma unroll
            for (int j = 0; j < 4; j++) C[nt][j] = 0.0f;

        const uint32_t axh = x_b + (uint32_t)par * (2u * XB) + a_off;
        const uint32_t axl = axh + (uint32_t)XB;

        #pragma unroll
        for (int ks = 0; ks < KSTEPS; ks++) {
            uint32_t ah[4], al[4];
            LDSM_X4(ah, axh + ks * 32);
            LDSM_X4(al, axl + ks * 32);
            #pragma unroll
            for (int ntp = 0; ntp < 13; ntp++) {
                uint32_t bh[4], bl[4];
                uint32_t bo = b_off + (uint32_t)(ntp * 16 * SKPX * 2) + ks * 32;
                LDSM_X4(bh, wh_b + bo);
                LDSM_X4(bl, wl_b + bo);
                mma16816(C[2 * ntp], ah, bh);
                mma16816(C[2 * ntp], al, bh);
                mma16816(C[2 * ntp], ah, bl);
                if (2 * ntp + 1 < 25) {
                    mma16816(C[2 * ntp + 1], ah, bh + 2);
                    mma16816(C[2 * ntp + 1], al, bh + 2);
                    mma16816(C[2 * ntp + 1], ah, bl + 2);
                }
            }
        }

        // epilogue: add bias, store fp32
        float* out0 = g_xp + (size_t)(tile * 128 + m0 + g) * G4 + hf * NH;
        float* out1 = out0 + 8 * G4;
        #pragma unroll
        for (int nt = 0; nt < 25; nt++) {
            int col = nt * 8 + t4 * 2;
            float2 b2 = *(float2*)(bs + col);
            *(float2*)(out0 + col) = make_float2(C[nt][0] + b2.x, C[nt][1] + b2.y);
            *(float2*)(out1 + col) = make_float2(C[nt][2] + b2.x, C[nt][3] + b2.y);
        }
        par ^= 1;
    }
}

// ======================================================================
// Tensor-core recurrent scan v4: 2-TERM split (h hi+lo x W-hi only).
// Dropped term Sum(a*Wlo) ~ 3e-4 abs on preactivations -> est rel_err ~1e-4.
// MMA count -33%, B-fragment smem traffic -50%, Wlo buffer deleted
// (smem 222.7KB -> 126.7KB). Otherwise identical to the R12 scan.
// ======================================================================
#define SKP 120                      // smem K stride (elements)
#define SWB (G4 * SKP * 2)           // 96000 B, W-hi buffer
#define SAB (32 * SKP * 2)           // 7680 B per h buffer

__global__ __launch_bounds__(512) void lstm_scan_mma(
    const float* __restrict__ Whh, int mode)
{
    extern __shared__ char sm[];
    char* Whi   = sm;
    char* Abase = Whi + SWB;         // 2 parity buffers x (hi, lo)

    const int tid  = threadIdx.x;
    const int wid  = tid >> 5;
    const int lane = tid & 31;
    const int g    = lane >> 2;
    const int t4   = lane & 3;
    const int b0   = blockIdx.x * 32;

    {
        uint32_t* z = (uint32_t*)sm;
        int tot = (SWB + 4 * SAB) / 4;
        for (int i = tid; i < tot; i += 512) z[i] = 0;
    }
    __syncthreads();

    // fill W-hi, gate-interleaved: slot n' = unit*4+gate <- row gate*100+unit
    for (int i4 = tid; i4 < G4 * (HDIM / 4); i4 += 512) {
        int n = i4 / (HDIM / 4), kq = i4 - n * (HDIM / 4);
        int unit = n >> 2, gate = n & 3;
        float4 v = *(const float4*)(Whh + (size_t)(gate * HDIM + unit) * HDIM + kq * 4);
        uint32_t* ph = (uint32_t*)(Whi + (n * SKP + kq * 4) * 2);
        ph[0] = pack_bf2(__bfloat162float(__float2bfloat16(v.x)),
                         __bfloat162float(__float2bfloat16(v.y)));
        ph[1] = pack_bf2(__bfloat162float(__float2bfloat16(v.z)),
                         __bfloat162float(__float2bfloat16(v.w)));
    }
    __syncthreads();

    const uint32_t smb  = smem_u32(sm);
    const uint32_t wh_b = smb;
    const uint32_t a_b  = smb + (uint32_t)SWB;

    const int mi     = wid & 1;
    const int ncol   = wid >> 1;                    // 0..7
    const int m0     = mi * 16;
    const int NT     = (ncol < 2) ? 7 : 6;
    const int tstart = (ncol < 2) ? ncol * 7 : 14 + (ncol - 2) * 6;
    const bool evn   = (t4 & 1) == 0;

    const int row0 = m0 + g;
    const int row1 = row0 + 8;

    float c[7][2];
    #pragma unroll
    for (int nt = 0; nt < 7; nt++) { c[nt][0] = 0.0f; c[nt][1] = 0.0f; }

    // ldmatrix fragment addresses
    const uint32_t a_off = (uint32_t)((m0 + (lane & 7) + ((lane >> 3) & 1) * 8) * SKP * 2
                                      + ((lane >> 4) & 1) * 16);
    const uint32_t b_base = (uint32_t)((tstart * 8 + (lane & 7) + ((lane >> 4) & 1) * 8) * SKP * 2
                                       + ((lane >> 3) & 1) * 16);

    int par = 0;
    for (int t = 0; t < TDIM; t++) {
        __nv_bfloat16* AhW = (__nv_bfloat16*)(Abase + (par ^ 1) * (2 * SAB));
        __nv_bfloat16* AlW = AhW + SAB / 2;

        // accumulators initialized from x-projection (gate-interleaved, coalesced)
        float C[7][4];
        {
            const float* p0 = g_xp + ((size_t)(b0 + row0) * TDIM + t) * G4 + tstart * 8 + t4 * 2;
            const float* p1 = g_xp + ((size_t)(b0 + row1) * TDIM + t) * G4 + tstart * 8 + t4 * 2;
            #pragma unroll
            for (int nt = 0; nt < 7; nt++) {
                if (nt < NT) {
                    float2 v0 = *(const float2*)(p0 + nt * 8);
                    float2 v1 = *(const float2*)(p1 + nt * 8);
                    C[nt][0] = v0.x; C[nt][1] = v0.y;
                    C[nt][2] = v1.x; C[nt][3] = v1.y;
                }
            }
        }

        const uint32_t axh = a_b + (uint32_t)par * (2u * SAB) + a_off;
        const uint32_t axl = axh + (uint32_t)SAB;

        #pragma unroll
        for (int ks = 0; ks < 7; ks++) {
            uint32_t ah[4], al[4];
            LDSM_X4(ah, axh + ks * 32);
            LDSM_X4(al, axl + ks * 32);
            #pragma unroll
            for (int p = 0; p < 4; p++) {
                if (2 * p < NT) {
                    uint32_t bh[4];
                    uint32_t bo = b_base + (uint32_t)(p * 16 * SKP * 2) + ks * 32;
                    LDSM_X4(bh, wh_b + bo);
                    mma16816(C[2 * p], ah, bh);
                    mma16816(C[2 * p], al, bh);
                    if (2 * p + 1 < NT) {
                        mma16816(C[2 * p + 1], ah, bh + 2);
                        mma16816(C[2 * p + 1], al, bh + 2);
                    }
                }
            }
        }

        // gates -> c,h.  Lane pairs: even t4 holds (i,f), odd holds (g,o).
        #pragma unroll
        for (int nt = 0; nt < 7; nt++) {
            if (nt < NT) {
                const int u = (tstart + nt) * 2 + (t4 >> 1);
                #pragma unroll
                for (int r = 0; r < 2; r++) {
                    float p0 = C[nt][2 * r];
                    float p1 = C[nt][2 * r + 1];
                    float q0 = evn ? p0 : (p0 + p0);
                    float s  = sigm(q0);
                    float a0 = evn ? s : (s + s - 1.0f);       // even: i ; odd: g
                    float a1 = sigm(p1);                       // even: f ; odd: o
                    float pa0 = __shfl_xor_sync(0xFFFFFFFFu, a0, 1);
                    float pa1 = __shfl_xor_sync(0xFFFFFFFFu, a1, 1);
                    float iv = evn ? a0  : pa0;
                    float fv = evn ? a1  : pa1;
                    float gv = evn ? pa0 : a0;
                    float ov = evn ? pa1 : a1;
                    float cn = fmaf(fv, c[nt][r], iv * gv);
                    c[nt][r] = cn;
                    float sc = sigm(cn + cn);
                    float hv = ov * (sc + sc - 1.0f);

                    if (evn) {
                        int lrow = r ? row1 : row0;
                        __nv_bfloat16 hh = __float2bfloat16(hv);
                        float hl = hv - __bfloat162float(hh);
                        AhW[lrow * SKP + u] = hh;
                        AlW[lrow * SKP + u] = __float2bfloat16(hl);
                        if (mode == 1) {
                            g_h1[((size_t)(b0 + lrow) * TDIM + t) * HDIM + u] = fmaxf(hv, 0.0f);
                        } else if (t == TDIM - 1) {
                            g_last[(b0 + lrow) * HDIM + u] = fmaxf(hv, 0.0f);
                        }
                    }
                }
            }
        }
        par ^= 1;
        __syncthreads();   // h(t) visible before next step's reads
    }
}

// ---------------- head: fc(8) + softmax ----------------
__global__ void head_kernel(const float* __restrict__ wfc,
                            const float* __restrict__ bfc,
                            float* __restrict__ out)
{
    int b = blockIdx.x * blockDim.x + threadIdx.x;
    if (b >= BDIM) return;
    const float* lr = g_last + b * HDIM;
    float lo[NCLS];
    #pragma unroll
    for (int cc = 0; cc < NCLS; cc++) {
        float s = bfc[cc];
        const float* wr = wfc + cc * HDIM;
        for (int u = 0; u < HDIM; u++) s = fmaf(lr[u], wr[u], s);
        lo[cc] = s;
    }
    float m = lo[0];
    #pragma unroll
    for (int cc = 1; cc < NCLS; cc++) m = fmaxf(m, lo[cc]);
    float sum = 0.0f;
    #pragma unroll
    for (int cc = 0; cc < NCLS; cc++) { lo[cc] = __expf(lo[cc] - m); sum += lo[cc]; }
    float inv = __fdividef(1.0f, sum);
    #pragma unroll
    for (int cc = 0; cc < NCLS; cc++) out[b * NCLS + cc] = lo[cc] * inv;
}

// ---------------- launch ----------------
extern "C" void kernel_launch(void* const* d_in, const int* in_sizes, int n_in,
                              void* d_out, int out_size)
{
    (void)in_sizes; (void)n_in; (void)out_size;
    const float* x     = (const float*)d_in[0];
    const float* w_ih1 = (const float*)d_in[1];
    const float* w_hh1 = (const float*)d_in[2];
    const float* b_ih1 = (const float*)d_in[3];
    const float* b_hh1 = (const float*)d_in[4];
    const float* w_ih2 = (const float*)d_in[5];
    const float* w_hh2 = (const float*)d_in[6];
    const float* b_ih2 = (const float*)d_in[7];
    const float* b_hh2 = (const float*)d_in[8];
    const float* w_fc  = (const float*)d_in[9];
    const float* b_fc  = (const float*)d_in[10];

    // smem: 1024 + 2*(208*SKPX*2) + 4*(128*SKPX*2)
    const int SZ64  = 1024 + 2 * (208 * 72  * 2) + 4 * (128 * 72  * 2);  // 134656
    const int SZ112 = 1024 + 2 * (208 * 120 * 2) + 4 * (128 * 120 * 2); // 223744
    const int SSC   = SWB + 4 * SAB;                                     // 126720

    cudaFuncSetAttribute((const void*)xproj_mma2<64, 72, 4>,
                         cudaFuncAttributeMaxDynamicSharedMemorySize, SZ64);
    cudaFuncSetAttribute((const void*)xproj_mma2<112, 120, 7>,
                         cudaFuncAttributeMaxDynamicSharedMemorySize, SZ112);
    cudaFuncSetAttribute((const void*)lstm_scan_mma,
                         cudaFuncAttributeMaxDynamicSharedMemorySize, SSC);

    void *xhi, *xlo, *hhi, *hlo;
    cudaGetSymbolAddress(&xhi, g_xhi);
    cudaGetSymbolAddress(&xlo, g_xlo);
    cudaGetSymbolAddress(&hhi, g_hhi);
    cudaGetSymbolAddress(&hlo, g_hlo);

    // prepass: x -> bf16 hi/lo
    prep_kernel<<<1024, 256>>>(x);
    // layer 1
    xproj_mma2<64, 72, 4><<<148, 256, SZ64>>>(
        (const __nv_bfloat16*)xhi, (const __nv_bfloat16*)xlo, w_ih1, 64, b_ih1, b_hh1);
    lstm_scan_mma<<<128, 512, SSC>>>(w_hh1, 1);
    // between layers: h1 fp32 -> bf16 hi/lo (+pad)
    prep2_kernel<<<1024, 256>>>();
    // layer 2
    xproj_mma2<112, 120, 7><<<148, 256, SZ112>>>(
        (const __nv_bfloat16*)hhi, (const __nv_bfloat16*)hlo, w_ih2, 100, b_ih2, b_hh2);
    lstm_scan_mma<<<128, 512, SSC>>>(w_hh2, 2);
    // head
    head_kernel<<<(BDIM + 255) / 256, 256>>>(w_fc, b_fc, (float*)d_out);
}

// round 15
// speedup vs baseline: 1.6166x; 1.1554x over previous
#include <cuda_runtime.h>
#include <cuda_bf16.h>
#include <cstdint>
#include <cstddef>

// Problem dims
#define BDIM 4096
#define TDIM 128
#define DDIM 64
#define HDIM 100
#define G4   400          // 4*H
#define NCLS 8
#define M1   (BDIM * TDIM)   // 524288 rows

// ---------------- scratch (device globals; no allocation allowed) ----------
__device__ __align__(16) float g_xp[(size_t)M1 * G4];     // 800 MB, reused by both layers
__device__ __align__(16) float g_h1[(size_t)M1 * HDIM];   // relu(h) of layer 1 (fp32)
__device__ __align__(16) float g_last[BDIM * HDIM];       // relu(h_T) of layer 2
// bf16 hi/lo inputs for the two projection GEMMs
__device__ __align__(16) __nv_bfloat16 g_xhi[(size_t)M1 * 64];    // layer-1 x hi
__device__ __align__(16) __nv_bfloat16 g_xlo[(size_t)M1 * 64];    // layer-1 x lo
__device__ __align__(16) __nv_bfloat16 g_hhi[(size_t)M1 * 112];   // layer-2 in hi, K padded to 112
__device__ __align__(16) __nv_bfloat16 g_hlo[(size_t)M1 * 112];   // layer-2 in lo

// ---------------- helpers ----------------
__device__ __forceinline__ float sigm(float x) {
    return __fdividef(1.0f, 1.0f + __expf(-x));
}
__device__ __forceinline__ uint32_t pack_bf2(float a, float b) {
    __nv_bfloat162 p = __floats2bfloat162_rn(a, b);
    return *reinterpret_cast<uint32_t*>(&p);
}
__device__ __forceinline__ uint32_t smem_u32(const void* p) {
    uint32_t a;
    asm("{ .reg .u64 t; cvta.to.shared.u64 t, %1; cvt.u32.u64 %0, t; }" : "=r"(a) : "l"(p));
    return a;
}

// m16n8k16 row.col bf16 MMA with fp32 accumulate (HMMA on Blackwell)
__device__ __forceinline__ void mma16816(float c[4], const uint32_t a[4], const uint32_t b[2]) {
    asm volatile(
        "mma.sync.aligned.m16n8k16.row.col.f32.bf16.bf16.f32 "
        "{%0,%1,%2,%3}, {%4,%5,%6,%7}, {%8,%9}, {%0,%1,%2,%3};"
        : "+f"(c[0]), "+f"(c[1]), "+f"(c[2]), "+f"(c[3])
        : "r"(a[0]), "r"(a[1]), "r"(a[2]), "r"(a[3]), "r"(b[0]), "r"(b[1]));
}

#define LDSM_X4(r, addr) \
    asm volatile("ldmatrix.sync.aligned.m8n8.x4.shared.b16 {%0,%1,%2,%3}, [%4];" \
        : "=r"((r)[0]), "=r"((r)[1]), "=r"((r)[2]), "=r"((r)[3]) : "r"(addr))

__device__ __forceinline__ void cp16(uint32_t dst, const void* src) {
    asm volatile("cp.async.cg.shared.global [%0], [%1], 16;" :: "r"(dst), "l"(src));
}
#define CP_COMMIT() asm volatile("cp.async.commit_group;" ::: "memory")
#define CP_WAIT1()  asm volatile("cp.async.wait_group 1;" ::: "memory")

// ======================================================================
// Prepass 1: x fp32 -> g_xhi/g_xlo bf16
// ======================================================================
__global__ void prep_kernel(const float* __restrict__ x)
{
    const size_t stride = (size_t)gridDim.x * blockDim.x;
    const size_t gt = (size_t)blockIdx.x * blockDim.x + threadIdx.x;

    const size_t N4 = (size_t)M1 * 64 / 4;
    const float4* x4 = (const float4*)x;
    uint2* oh = (uint2*)g_xhi;
    uint2* ol = (uint2*)g_xlo;
    for (size_t i = gt; i < N4; i += stride) {
        float4 v = x4[i];
        float h0 = __bfloat162float(__float2bfloat16(v.x));
        float h1 = __bfloat162float(__float2bfloat16(v.y));
        float h2 = __bfloat162float(__float2bfloat16(v.z));
        float h3 = __bfloat162float(__float2bfloat16(v.w));
        oh[i] = make_uint2(pack_bf2(h0, h1), pack_bf2(h2, h3));
        ol[i] = make_uint2(pack_bf2(v.x - h0, v.y - h1), pack_bf2(v.z - h2, v.w - h3));
    }
}

// ======================================================================
// Prepass 2: g_h1 fp32 -> g_hhi/g_hlo bf16, pad cols 100..111 zero
// ======================================================================
__global__ void prep2_kernel()
{
    const size_t stride = (size_t)gridDim.x * blockDim.x;
    const size_t gt = (size_t)blockIdx.x * blockDim.x + threadIdx.x;
    const size_t NQ = (size_t)M1 * 28;     // 28 quads of 4 per 112-wide row

    uint2* oh = (uint2*)g_hhi;
    uint2* ol = (uint2*)g_hlo;
    for (size_t i = gt; i < NQ; i += stride) {
        size_t r = i / 28;
        int u0 = (int)(i - r * 28) * 4;
        float4 v;
        if (u0 < 100) v = *(const float4*)(g_h1 + r * HDIM + u0);
        else          v = make_float4(0.f, 0.f, 0.f, 0.f);
        float h0 = __bfloat162float(__float2bfloat16(v.x));
        float h1 = __bfloat162float(__float2bfloat16(v.y));
        float h2 = __bfloat162float(__float2bfloat16(v.z));
        float h3 = __bfloat162float(__float2bfloat16(v.w));
        size_t o = r * 28 + (size_t)(u0 >> 2);
        oh[o] = make_uint2(pack_bf2(h0, h1), pack_bf2(h2, h3));
        ol[o] = make_uint2(pack_bf2(v.x - h0, v.y - h1), pack_bf2(v.z - h2, v.w - h3));
    }
}

// ======================================================================
// Input-projection GEMM v4: 2-TERM split (X hi+lo x W-hi bf16).
// g_xp = [Xhi+Xlo] @ Whi^T + (ba+bb); cp.async double-buffered, ldmatrix.x4.
// Gate-interleaved output (col' = unit*4 + gate); blockIdx&1 = gate half.
// W-lo buffer/MMAs deleted (-33% MMA vs R13).
// ======================================================================
template <int KG, int SKPX, int KSTEPS>
__global__ __launch_bounds__(256) void xproj_mma2(
    const __nv_bfloat16* __restrict__ Xhi, const __nv_bfloat16* __restrict__ Xlo,
    const float* __restrict__ W, int Kw,
    const float* __restrict__ ba, const float* __restrict__ bb)
{
    constexpr int NH  = 200;
    constexpr int NWR = 208;                 // padded W rows (ldmatrix x4 overread)
    constexpr int WB  = NWR * SKPX * 2;
    constexpr int XB  = 128 * SKPX * 2;
    constexpr int NCH = KG / 8;              // 16B chunks per row

    extern __shared__ char sm[];
    float* bs = (float*)sm;                  // [200] bias
    char* WhiP = sm + 1024;

    const int tid  = threadIdx.x;
    const int wid  = tid >> 5;
    const int lane = tid & 31;
    const int g    = lane >> 2;
    const int t4   = lane & 3;
    const int hf   = blockIdx.x & 1;
    const int cta  = blockIdx.x >> 1;

    const uint32_t smb  = smem_u32(sm);
    const uint32_t wh_b = smb + 1024;
    const uint32_t x_b  = wh_b + (uint32_t)WB;

    // zero W buffer (covers K padding + row padding)
    {
        uint32_t* z = (uint32_t*)WhiP;
        for (int i = tid; i < WB / 4; i += 256) z[i] = 0;
    }
    __syncthreads();

    // convert W-hi + bias; smem slot n <-> W row gate*100 + (hf*50 + n/4)
    {
        const int KQ = Kw / 4;
        char* Whi = WhiP;
        for (int i4 = tid; i4 < NH * KQ; i4 += 256) {
            int n = i4 / KQ, kq = i4 - n * KQ;
            int unit = hf * 50 + (n >> 2);
            int gate = n & 3;
            float4 v = *(const float4*)(W + (size_t)(gate * HDIM + unit) * Kw + kq * 4);
            uint32_t* ph = (uint32_t*)(Whi + (n * SKPX + kq * 4) * 2);
            ph[0] = pack_bf2(__bfloat162float(__float2bfloat16(v.x)),
                             __bfloat162float(__float2bfloat16(v.y)));
            ph[1] = pack_bf2(__bfloat162float(__float2bfloat16(v.z)),
                             __bfloat162float(__float2bfloat16(v.w)));
        }
        for (int n = tid; n < NH; n += 256) {
            int wrow = (n & 3) * HDIM + hf * 50 + (n >> 2);
            bs[n] = ba[wrow] + bb[wrow];
        }
    }

    auto issue = [&](int tile, int p) {
        uint32_t dh = x_b + (uint32_t)p * (2u * XB);
        uint32_t dl = dh + (uint32_t)XB;
        const __nv_bfloat16* sh = Xhi + (size_t)tile * 128 * KG;
        const __nv_bfloat16* sl = Xlo + (size_t)tile * 128 * KG;
        for (int i = tid; i < 128 * NCH; i += 256) {
            int r = i / NCH, c = i - r * NCH;
            uint32_t doff = (uint32_t)(r * SKPX + c * 8) * 2;
            size_t soff = (size_t)r * KG + c * 8;
            cp16(dh + doff, sh + soff);
            cp16(dl + doff, sl + soff);
        }
    };

    issue(cta, 0);
    CP_COMMIT();

    const int m0 = wid * 16;
    const uint32_t a_off = (uint32_t)((m0 + (lane & 7) + ((lane >> 3) & 1) * 8) * SKPX * 2
                                      + ((lane >> 4) & 1) * 16);
    const uint32_t b_off = (uint32_t)(((lane & 7) + ((lane >> 4) & 1) * 8) * SKPX * 2
                                      + ((lane >> 3) & 1) * 16);

    int par = 0;
    for (int tile = cta; tile < 4096; tile += 74) {
        __syncthreads();                 // buf[par^1] free (previous compute done)
        int nt2 = tile + 74;
        if (nt2 < 4096) issue(nt2, par ^ 1);
        CP_COMMIT();
        CP_WAIT1();                      // buf[par] group complete (this thread)
        __syncthreads();                 // ... and for all threads

        float C[25][4];
        #pragma unroll
        for (int nt = 0; nt < 25; nt++)
            #pragma unroll
            for (int j = 0; j < 4; j++) C[nt][j] = 0.0f;

        const uint32_t axh = x_b + (uint32_t)par * (2u * XB) + a_off;
        const uint32_t axl = axh + (uint32_t)XB;

        #pragma unroll
        for (int ks = 0; ks < KSTEPS; ks++) {
            uint32_t ah[4], al[4];
            LDSM_X4(ah, axh + ks * 32);
            LDSM_X4(al, axl + ks * 32);
            #pragma unroll
            for (int ntp = 0; ntp < 13; ntp++) {
                uint32_t bh[4];
                uint32_t bo = b_off + (uint32_t)(ntp * 16 * SKPX * 2) + ks * 32;
                LDSM_X4(bh, wh_b + bo);
                mma16816(C[2 * ntp], ah, bh);
                mma16816(C[2 * ntp], al, bh);
                if (2 * ntp + 1 < 25) {
                    mma16816(C[2 * ntp + 1], ah, bh + 2);
                    mma16816(C[2 * ntp + 1], al, bh + 2);
                }
            }
        }

        // epilogue: add bias, store fp32
        float* out0 = g_xp + (size_t)(tile * 128 + m0 + g) * G4 + hf * NH;
        float* out1 = out0 + 8 * G4;
        #pragma unroll
        for (int nt = 0; nt < 25; nt++) {
            int col = nt * 8 + t4 * 2;
            float2 b2 = *(float2*)(bs + col);
            *(float2*)(out0 + col) = make_float2(C[nt][0] + b2.x, C[nt][1] + b2.y);
            *(float2*)(out1 + col) = make_float2(C[nt][2] + b2.x, C[nt][3] + b2.y);
        }
        par ^= 1;
    }
}

// ======================================================================
// Tensor-core recurrent scan v5: 1-TERM (h bf16 x W-hi bf16).
// h stored as plain bf16 (no lo correction); MMA count -50% vs v4,
// A-fragment LDSM -50%, h-lo conversion/stores deleted. smem = 111.4KB.
// ======================================================================
#define SKP 120                      // smem K stride (elements)
#define SWB (G4 * SKP * 2)           // 96000 B, W-hi buffer
#define SAB (32 * SKP * 2)           // 7680 B per h buffer

__global__ __launch_bounds__(512) void lstm_scan_mma(
    const float* __restrict__ Whh, int mode)
{
    extern __shared__ char sm[];
    char* Whi   = sm;
    char* Abase = Whi + SWB;         // 2 parity buffers (h bf16)

    const int tid  = threadIdx.x;
    const int wid  = tid >> 5;
    const int lane = tid & 31;
    const int g    = lane >> 2;
    const int t4   = lane & 3;
    const int b0   = blockIdx.x * 32;

    {
        uint32_t* z = (uint32_t*)sm;
        int tot = (SWB + 2 * SAB) / 4;
        for (int i = tid; i < tot; i += 512) z[i] = 0;
    }
    __syncthreads();

    // fill W-hi, gate-interleaved: slot n' = unit*4+gate <- row gate*100+unit
    for (int i4 = tid; i4 < G4 * (HDIM / 4); i4 += 512) {
        int n = i4 / (HDIM / 4), kq = i4 - n * (HDIM / 4);
        int unit = n >> 2, gate = n & 3;
        float4 v = *(const float4*)(Whh + (size_t)(gate * HDIM + unit) * HDIM + kq * 4);
        uint32_t* ph = (uint32_t*)(Whi + (n * SKP + kq * 4) * 2);
        ph[0] = pack_bf2(__bfloat162float(__float2bfloat16(v.x)),
                         __bfloat162float(__float2bfloat16(v.y)));
        ph[1] = pack_bf2(__bfloat162float(__float2bfloat16(v.z)),
                         __bfloat162float(__float2bfloat16(v.w)));
    }
    __syncthreads();

    const uint32_t smb  = smem_u32(sm);
    const uint32_t wh_b = smb;
    const uint32_t a_b  = smb + (uint32_t)SWB;

    const int mi     = wid & 1;
    const int ncol   = wid >> 1;                    // 0..7
    const int m0     = mi * 16;
    const int NT     = (ncol < 2) ? 7 : 6;
    const int tstart = (ncol < 2) ? ncol * 7 : 14 + (ncol - 2) * 6;
    const bool evn   = (t4 & 1) == 0;

    const int row0 = m0 + g;
    const int row1 = row0 + 8;

    float c[7][2];
    #pragma unroll
    for (int nt = 0; nt < 7; nt++) { c[nt][0] = 0.0f; c[nt][1] = 0.0f; }

    // ldmatrix fragment addresses
    const uint32_t a_off = (uint32_t)((m0 + (lane & 7) + ((lane >> 3) & 1) * 8) * SKP * 2
                                      + ((lane >> 4) & 1) * 16);
    const uint32_t b_base = (uint32_t)((tstart * 8 + (lane & 7) + ((lane >> 4) & 1) * 8) * SKP * 2
                                       + ((lane >> 3) & 1) * 16);

    int par = 0;
    for (int t = 0; t < TDIM; t++) {
        __nv_bfloat16* AhW = (__nv_bfloat16*)(Abase + (par ^ 1) * SAB);

        // accumulators initialized from x-projection (gate-interleaved, coalesced)
        float C[7][4];
        {
            const float* p0 = g_xp + ((size_t)(b0 + row0) * TDIM + t) * G4 + tstart * 8 + t4 * 2;
            const float* p1 = g_xp + ((size_t)(b0 + row1) * TDIM + t) * G4 + tstart * 8 + t4 * 2;
            #pragma unroll
            for (int nt = 0; nt < 7; nt++) {
                if (nt < NT) {
                    float2 v0 = *(const float2*)(p0 + nt * 8);
                    float2 v1 = *(const float2*)(p1 + nt * 8);
                    C[nt][0] = v0.x; C[nt][1] = v0.y;
                    C[nt][2] = v1.x; C[nt][3] = v1.y;
                }
            }
        }

        const uint32_t axh = a_b + (uint32_t)par * (uint32_t)SAB + a_off;

        #pragma unroll
        for (int ks = 0; ks < 7; ks++) {
            uint32_t ah[4];
            LDSM_X4(ah, axh + ks * 32);
            #pragma unroll
            for (int p = 0; p < 4; p++) {
                if (2 * p < NT) {
                    uint32_t bh[4];
                    uint32_t bo = b_base + (uint32_t)(p * 16 * SKP * 2) + ks * 32;
                    LDSM_X4(bh, wh_b + bo);
                    mma16816(C[2 * p], ah, bh);
                    if (2 * p + 1 < NT) {
                        mma16816(C[2 * p + 1], ah, bh + 2);
                    }
                }
            }
        }

        // gates -> c,h.  Lane pairs: even t4 holds (i,f), odd holds (g,o).
        #pragma unroll
        for (int nt = 0; nt < 7; nt++) {
            if (nt < NT) {
                const int u = (tstart + nt) * 2 + (t4 >> 1);
                #pragma unroll
                for (int r = 0; r < 2; r++) {
                    float p0 = C[nt][2 * r];
                    float p1 = C[nt][2 * r + 1];
                    float q0 = evn ? p0 : (p0 + p0);
                    float s  = sigm(q0);
                    float a0 = evn ? s : (s + s - 1.0f);       // even: i ; odd: g
                    float a1 = sigm(p1);                       // even: f ; odd: o
                    float pa0 = __shfl_xor_sync(0xFFFFFFFFu, a0, 1);
                    float pa1 = __shfl_xor_sync(0xFFFFFFFFu, a1, 1);
                    float iv = evn ? a0  : pa0;
                    float fv = evn ? a1  : pa1;
                    float gv = evn ? pa0 : a0;
                    float ov = evn ? pa1 : a1;
                    float cn = fmaf(fv, c[nt][r], iv * gv);
                    c[nt][r] = cn;
                    float sc = sigm(cn + cn);
                    float hv = ov * (sc + sc - 1.0f);

                    if (evn) {
                        int lrow = r ? row1 : row0;
                        AhW[lrow * SKP + u] = __float2bfloat16(hv);
                        if (mode == 1) {
                            g_h1[((size_t)(b0 + lrow) * TDIM + t) * HDIM + u] = fmaxf(hv, 0.0f);
                        } else if (t == TDIM - 1) {
                            g_last[(b0 + lrow) * HDIM + u] = fmaxf(hv, 0.0f);
                        }
                    }
                }
            }
        }
        par ^= 1;
        __syncthreads();   // h(t) visible before next step's reads
    }
}

// ---------------- head: fc(8) + softmax ----------------
__global__ void head_kernel(const float* __restrict__ wfc,
                            const float* __restrict__ bfc,
                            float* __restrict__ out)
{
    int b = blockIdx.x * blockDim.x + threadIdx.x;
    if (b >= BDIM) return;
    const float* lr = g_last + b * HDIM;
    float lo[NCLS];
    #pragma unroll
    for (int cc = 0; cc < NCLS; cc++) {
        float s = bfc[cc];
        const float* wr = wfc + cc * HDIM;
        for (int u = 0; u < HDIM; u++) s = fmaf(lr[u], wr[u], s);
        lo[cc] = s;
    }
    float m = lo[0];
    #pragma unroll
    for (int cc = 1; cc < NCLS; cc++) m = fmaxf(m, lo[cc]);
    float sum = 0.0f;
    #pragma unroll
    for (int cc = 0; cc < NCLS; cc++) { lo[cc] = __expf(lo[cc] - m); sum += lo[cc]; }
    float inv = __fdividef(1.0f, sum);
    #pragma unroll
    for (int cc = 0; cc < NCLS; cc++) out[b * NCLS + cc] = lo[cc] * inv;
}

// ---------------- launch ----------------
extern "C" void kernel_launch(void* const* d_in, const int* in_sizes, int n_in,
                              void* d_out, int out_size)
{
    (void)in_sizes; (void)n_in; (void)out_size;
    const float* x     = (const float*)d_in[0];
    const float* w_ih1 = (const float*)d_in[1];
    const float* w_hh1 = (const float*)d_in[2];
    const float* b_ih1 = (const float*)d_in[3];
    const float* b_hh1 = (const float*)d_in[4];
    const float* w_ih2 = (const float*)d_in[5];
    const float* w_hh2 = (const float*)d_in[6];
    const float* b_ih2 = (const float*)d_in[7];
    const float* b_hh2 = (const float*)d_in[8];
    const float* w_fc  = (const float*)d_in[9];
    const float* b_fc  = (const float*)d_in[10];

    // smem: 1024 + (208*SKPX*2) + 4*(128*SKPX*2)
    const int SZ64  = 1024 + (208 * 72  * 2) + 4 * (128 * 72  * 2);  // 104704
    const int SZ112 = 1024 + (208 * 120 * 2) + 4 * (128 * 120 * 2); // 173824
    const int SSC   = SWB + 2 * SAB;                                 // 111360

    cudaFuncSetAttribute((const void*)xproj_mma2<64, 72, 4>,
                         cudaFuncAttributeMaxDynamicSharedMemorySize, SZ64);
    cudaFuncSetAttribute((const void*)xproj_mma2<112, 120, 7>,
                         cudaFuncAttributeMaxDynamicSharedMemorySize, SZ112);
    cudaFuncSetAttribute((const void*)lstm_scan_mma,
                         cudaFuncAttributeMaxDynamicSharedMemorySize, SSC);

    void *xhi, *xlo, *hhi, *hlo;
    cudaGetSymbolAddress(&xhi, g_xhi);
    cudaGetSymbolAddress(&xlo, g_xlo);
    cudaGetSymbolAddress(&hhi, g_hhi);
    cudaGetSymbolAddress(&hlo, g_hlo);

    // prepass: x -> bf16 hi/lo
    prep_kernel<<<1024, 256>>>(x);
    // layer 1
    xproj_mma2<64, 72, 4><<<148, 256, SZ64>>>(
        (const __nv_bfloat16*)xhi, (const __nv_bfloat16*)xlo, w_ih1, 64, b_ih1, b_hh1);
    lstm_scan_mma<<<128, 512, SSC>>>(w_hh1, 1);
    // between layers: h1 fp32 -> bf16 hi/lo (+pad)
    prep2_kernel<<<1024, 256>>>();
    // layer 2
    xproj_mma2<112, 120, 7><<<148, 256, SZ112>>>(
        (const __nv_bfloat16*)hhi, (const __nv_bfloat16*)hlo, w_ih2, 100, b_ih2, b_hh2);
    lstm_scan_mma<<<128, 512, SSC>>>(w_hh2, 2);
    // head
    head_kernel<<<(BDIM + 255) / 256, 256>>>(w_fc, b_fc, (float*)d_out);
}

// round 16
// speedup vs baseline: 1.6561x; 1.0244x over previous
#include <cuda_runtime.h>
#include <cuda_bf16.h>
#include <cstdint>
#include <cstddef>

// Problem dims
#define BDIM 4096
#define TDIM 128
#define DDIM 64
#define HDIM 100
#define G4   400          // 4*H
#define NCLS 8
#define M1   (BDIM * TDIM)   // 524288 rows

// ---------------- scratch (device globals; no allocation allowed) ----------
__device__ __align__(16) float g_xp[(size_t)M1 * G4];     // 800 MB, reused by both layers
__device__ __align__(16) float g_h1[(size_t)M1 * HDIM];   // relu(h) of layer 1 (fp32)
__device__ __align__(16) float g_last[BDIM * HDIM];       // relu(h_T) of layer 2
// bf16 hi/lo inputs for the two projection GEMMs
__device__ __align__(16) __nv_bfloat16 g_xhi[(size_t)M1 * 64];    // layer-1 x hi
__device__ __align__(16) __nv_bfloat16 g_xlo[(size_t)M1 * 64];    // layer-1 x lo
__device__ __align__(16) __nv_bfloat16 g_hhi[(size_t)M1 * 112];   // layer-2 in hi, K padded to 112
__device__ __align__(16) __nv_bfloat16 g_hlo[(size_t)M1 * 112];   // layer-2 in lo

// ---------------- helpers ----------------
__device__ __forceinline__ float sigm(float x) {
    return __fdividef(1.0f, 1.0f + __expf(-x));
}
__device__ __forceinline__ uint32_t pack_bf2(float a, float b) {
    __nv_bfloat162 p = __floats2bfloat162_rn(a, b);
    return *reinterpret_cast<uint32_t*>(&p);
}
__device__ __forceinline__ uint32_t smem_u32(const void* p) {
    uint32_t a;
    asm("{ .reg .u64 t; cvta.to.shared.u64 t, %1; cvt.u32.u64 %0, t; }" : "=r"(a) : "l"(p));
    return a;
}

// m16n8k16 row.col bf16 MMA with fp32 accumulate (HMMA on Blackwell)
__device__ __forceinline__ void mma16816(float c[4], const uint32_t a[4], const uint32_t b[2]) {
    asm volatile(
        "mma.sync.aligned.m16n8k16.row.col.f32.bf16.bf16.f32 "
        "{%0,%1,%2,%3}, {%4,%5,%6,%7}, {%8,%9}, {%0,%1,%2,%3};"
        : "+f"(c[0]), "+f"(c[1]), "+f"(c[2]), "+f"(c[3])
        : "r"(a[0]), "r"(a[1]), "r"(a[2]), "r"(a[3]), "r"(b[0]), "r"(b[1]));
}

#define LDSM_X4(r, addr) \
    asm volatile("ldmatrix.sync.aligned.m8n8.x4.shared.b16 {%0,%1,%2,%3}, [%4];" \
        : "=r"((r)[0]), "=r"((r)[1]), "=r"((r)[2]), "=r"((r)[3]) : "r"(addr))

__device__ __forceinline__ void cp16(uint32_t dst, const void* src) {
    asm volatile("cp.async.cg.shared.global [%0], [%1], 16;" :: "r"(dst), "l"(src));
}
#define CP_COMMIT() asm volatile("cp.async.commit_group;" ::: "memory")
#define CP_WAIT1()  asm volatile("cp.async.wait_group 1;" ::: "memory")

// ======================================================================
// Prepass 1: x fp32 -> g_xhi/g_xlo bf16
// ======================================================================
__global__ void prep_kernel(const float* __restrict__ x)
{
    const size_t stride = (size_t)gridDim.x * blockDim.x;
    const size_t gt = (size_t)blockIdx.x * blockDim.x + threadIdx.x;

    const size_t N4 = (size_t)M1 * 64 / 4;
    const float4* x4 = (const float4*)x;
    uint2* oh = (uint2*)g_xhi;
    uint2* ol = (uint2*)g_xlo;
    for (size_t i = gt; i < N4; i += stride) {
        float4 v = x4[i];
        float h0 = __bfloat162float(__float2bfloat16(v.x));
        float h1 = __bfloat162float(__float2bfloat16(v.y));
        float h2 = __bfloat162float(__float2bfloat16(v.z));
        float h3 = __bfloat162float(__float2bfloat16(v.w));
        oh[i] = make_uint2(pack_bf2(h0, h1), pack_bf2(h2, h3));
        ol[i] = make_uint2(pack_bf2(v.x - h0, v.y - h1), pack_bf2(v.z - h2, v.w - h3));
    }
}

// ======================================================================
// Prepass 2: g_h1 fp32 -> g_hhi/g_hlo bf16, pad cols 100..111 zero
// ======================================================================
__global__ void prep2_kernel()
{
    const size_t stride = (size_t)gridDim.x * blockDim.x;
    const size_t gt = (size_t)blockIdx.x * blockDim.x + threadIdx.x;
    const size_t NQ = (size_t)M1 * 28;     // 28 quads of 4 per 112-wide row

    uint2* oh = (uint2*)g_hhi;
    uint2* ol = (uint2*)g_hlo;
    for (size_t i = gt; i < NQ; i += stride) {
        size_t r = i / 28;
        int u0 = (int)(i - r * 28) * 4;
        float4 v;
        if (u0 < 100) v = *(const float4*)(g_h1 + r * HDIM + u0);
        else          v = make_float4(0.f, 0.f, 0.f, 0.f);
        float h0 = __bfloat162float(__float2bfloat16(v.x));
        float h1 = __bfloat162float(__float2bfloat16(v.y));
        float h2 = __bfloat162float(__float2bfloat16(v.z));
        float h3 = __bfloat162float(__float2bfloat16(v.w));
        size_t o = r * 28 + (size_t)(u0 >> 2);
        oh[o] = make_uint2(pack_bf2(h0, h1), pack_bf2(h2, h3));
        ol[o] = make_uint2(pack_bf2(v.x - h0, v.y - h1), pack_bf2(v.z - h2, v.w - h3));
    }
}

// ======================================================================
// Input-projection GEMM v4 (unchanged from R15): 2-TERM split.
// ======================================================================
template <int KG, int SKPX, int KSTEPS>
__global__ __launch_bounds__(256) void xproj_mma2(
    const __nv_bfloat16* __restrict__ Xhi, const __nv_bfloat16* __restrict__ Xlo,
    const float* __restrict__ W, int Kw,
    const float* __restrict__ ba, const float* __restrict__ bb)
{
    constexpr int NH  = 200;
    constexpr int NWR = 208;                 // padded W rows (ldmatrix x4 overread)
    constexpr int WB  = NWR * SKPX * 2;
    constexpr int XB  = 128 * SKPX * 2;
    constexpr int NCH = KG / 8;              // 16B chunks per row

    extern __shared__ char sm[];
    float* bs = (float*)sm;                  // [200] bias
    char* WhiP = sm + 1024;

    const int tid  = threadIdx.x;
    const int wid  = tid >> 5;
    const int lane = tid & 31;
    const int g    = lane >> 2;
    const int t4   = lane & 3;
    const int hf   = blockIdx.x & 1;
    const int cta  = blockIdx.x >> 1;

    const uint32_t smb  = smem_u32(sm);
    const uint32_t wh_b = smb + 1024;
    const uint32_t x_b  = wh_b + (uint32_t)WB;

    // zero W buffer (covers K padding + row padding)
    {
        uint32_t* z = (uint32_t*)WhiP;
        for (int i = tid; i < WB / 4; i += 256) z[i] = 0;
    }
    __syncthreads();

    // convert W-hi + bias; smem slot n <-> W row gate*100 + (hf*50 + n/4)
    {
        const int KQ = Kw / 4;
        char* Whi = WhiP;
        for (int i4 = tid; i4 < NH * KQ; i4 += 256) {
            int n = i4 / KQ, kq = i4 - n * KQ;
            int unit = hf * 50 + (n >> 2);
            int gate = n & 3;
            float4 v = *(const float4*)(W + (size_t)(gate * HDIM + unit) * Kw + kq * 4);
            uint32_t* ph = (uint32_t*)(Whi + (n * SKPX + kq * 4) * 2);
            ph[0] = pack_bf2(__bfloat162float(__float2bfloat16(v.x)),
                             __bfloat162float(__float2bfloat16(v.y)));
            ph[1] = pack_bf2(__bfloat162float(__float2bfloat16(v.z)),
                             __bfloat162float(__float2bfloat16(v.w)));
        }
        for (int n = tid; n < NH; n += 256) {
            int wrow = (n & 3) * HDIM + hf * 50 + (n >> 2);
            bs[n] = ba[wrow] + bb[wrow];
        }
    }

    auto issue = [&](int tile, int p) {
        uint32_t dh = x_b + (uint32_t)p * (2u * XB);
        uint32_t dl = dh + (uint32_t)XB;
        const __nv_bfloat16* sh = Xhi + (size_t)tile * 128 * KG;
        const __nv_bfloat16* sl = Xlo + (size_t)tile * 128 * KG;
        for (int i = tid; i < 128 * NCH; i += 256) {
            int r = i / NCH, c = i - r * NCH;
            uint32_t doff = (uint32_t)(r * SKPX + c * 8) * 2;
            size_t soff = (size_t)r * KG + c * 8;
            cp16(dh + doff, sh + soff);
            cp16(dl + doff, sl + soff);
        }
    };

    issue(cta, 0);
    CP_COMMIT();

    const int m0 = wid * 16;
    const uint32_t a_off = (uint32_t)((m0 + (lane & 7) + ((lane >> 3) & 1) * 8) * SKPX * 2
                                      + ((lane >> 4) & 1) * 16);
    const uint32_t b_off = (uint32_t)(((lane & 7) + ((lane >> 4) & 1) * 8) * SKPX * 2
                                      + ((lane >> 3) & 1) * 16);

    int par = 0;
    for (int tile = cta; tile < 4096; tile += 74) {
        __syncthreads();                 // buf[par^1] free (previous compute done)
        int nt2 = tile + 74;
        if (nt2 < 4096) issue(nt2, par ^ 1);
        CP_COMMIT();
        CP_WAIT1();                      // buf[par] group complete (this thread)
        __syncthreads();                 // ... and for all threads

        float C[25][4];
        #pragma unroll
        for (int nt = 0; nt < 25; nt++)
            #pragma unroll
            for (int j = 0; j < 4; j++) C[nt][j] = 0.0f;

        const uint32_t axh = x_b + (uint32_t)par * (2u * XB) + a_off;
        const uint32_t axl = axh + (uint32_t)XB;

        #pragma unroll
        for (int ks = 0; ks < KSTEPS; ks++) {
            uint32_t ah[4], al[4];
            LDSM_X4(ah, axh + ks * 32);
            LDSM_X4(al, axl + ks * 32);
            #pragma unroll
            for (int ntp = 0; ntp < 13; ntp++) {
                uint32_t bh[4];
                uint32_t bo = b_off + (uint32_t)(ntp * 16 * SKPX * 2) + ks * 32;
                LDSM_X4(bh, wh_b + bo);
                mma16816(C[2 * ntp], ah, bh);
                mma16816(C[2 * ntp], al, bh);
                if (2 * ntp + 1 < 25) {
                    mma16816(C[2 * ntp + 1], ah, bh + 2);
                    mma16816(C[2 * ntp + 1], al, bh + 2);
                }
            }
        }

        // epilogue: add bias, store fp32
        float* out0 = g_xp + (size_t)(tile * 128 + m0 + g) * G4 + hf * NH;
        float* out1 = out0 + 8 * G4;
        #pragma unroll
        for (int nt = 0; nt < 25; nt++) {
            int col = nt * 8 + t4 * 2;
            float2 b2 = *(float2*)(bs + col);
            *(float2*)(out0 + col) = make_float2(C[nt][0] + b2.x, C[nt][1] + b2.y);
            *(float2*)(out1 + col) = make_float2(C[nt][2] + b2.x, C[nt][3] + b2.y);
        }
        par ^= 1;
    }
}

// ======================================================================
// Tensor-core recurrent scan v6: 2 CTAs/SM + cross-step xp prefetch.
// grid 256 x 256 threads; M-tile = 16 batch rows/CTA (8 warps = 8 n-cols).
// W-hi resident per CTA (96KB); h double-buffered bf16; 1 barrier/step.
// xv(t+1) register-prefetched during step t (hides DRAM latency).
// smem/CTA = 103.7KB -> two independent CTAs per SM overlap phases.
// ======================================================================
#define SKP 120                      // smem K stride (elements)
#define SWB (G4 * SKP * 2)           // 96000 B, W-hi buffer
#define SAB2 (16 * SKP * 2)          // 3840 B per h buffer (16 rows)

__global__ __launch_bounds__(256, 2) void lstm_scan_mma(
    const float* __restrict__ Whh, int mode)
{
    extern __shared__ char sm[];
    char* Whi   = sm;
    char* Abase = Whi + SWB;         // 2 parity buffers (h bf16)

    const int tid  = threadIdx.x;
    const int wid  = tid >> 5;
    const int lane = tid & 31;
    const int g    = lane >> 2;
    const int t4   = lane & 3;
    const int b0   = blockIdx.x * 16;

    {
        uint32_t* z = (uint32_t*)sm;
        int tot = (SWB + 2 * SAB2) / 4;
        for (int i = tid; i < tot; i += 256) z[i] = 0;
    }
    __syncthreads();

    // fill W-hi, gate-interleaved: slot n' = unit*4+gate <- row gate*100+unit
    for (int i4 = tid; i4 < G4 * (HDIM / 4); i4 += 256) {
        int n = i4 / (HDIM / 4), kq = i4 - n * (HDIM / 4);
        int unit = n >> 2, gate = n & 3;
        float4 v = *(const float4*)(Whh + (size_t)(gate * HDIM + unit) * HDIM + kq * 4);
        uint32_t* ph = (uint32_t*)(Whi + (n * SKP + kq * 4) * 2);
        ph[0] = pack_bf2(__bfloat162float(__float2bfloat16(v.x)),
                         __bfloat162float(__float2bfloat16(v.y)));
        ph[1] = pack_bf2(__bfloat162float(__float2bfloat16(v.z)),
                         __bfloat162float(__float2bfloat16(v.w)));
    }
    __syncthreads();

    const uint32_t smb  = smem_u32(sm);
    const uint32_t wh_b = smb;
    const uint32_t a_b  = smb + (uint32_t)SWB;

    const int ncol   = wid;                         // 0..7
    const int NT     = (ncol < 2) ? 7 : 6;
    const int tstart = (ncol < 2) ? ncol * 7 : 14 + (ncol - 2) * 6;
    const bool evn   = (t4 & 1) == 0;

    const int row0 = g;            // local rows (M-tile = 16)
    const int row1 = g + 8;

    float c[7][2];
    #pragma unroll
    for (int nt = 0; nt < 7; nt++) { c[nt][0] = 0.0f; c[nt][1] = 0.0f; }

    // ldmatrix fragment addresses (m0 = 0)
    const uint32_t a_off = (uint32_t)(((lane & 7) + ((lane >> 3) & 1) * 8) * SKP * 2
                                      + ((lane >> 4) & 1) * 16);
    const uint32_t b_base = (uint32_t)((tstart * 8 + (lane & 7) + ((lane >> 4) & 1) * 8) * SKP * 2
                                       + ((lane >> 3) & 1) * 16);

    const float* xp0 = g_xp + (size_t)(b0 + row0) * TDIM * G4 + tstart * 8 + t4 * 2;
    const float* xp1 = g_xp + (size_t)(b0 + row1) * TDIM * G4 + tstart * 8 + t4 * 2;

    // prefetch xv for t = 0
    float2 xv0[7], xv1[7];
    #pragma unroll
    for (int nt = 0; nt < 7; nt++) {
        if (nt < NT) {
            xv0[nt] = *(const float2*)(xp0 + nt * 8);
            xv1[nt] = *(const float2*)(xp1 + nt * 8);
        }
    }

    int par = 0;
    for (int t = 0; t < TDIM; t++) {
        __nv_bfloat16* AhW = (__nv_bfloat16*)(Abase + (par ^ 1) * SAB2);

        // consume prefetched xv into accumulators
        float C[7][4];
        #pragma unroll
        for (int nt = 0; nt < 7; nt++) {
            if (nt < NT) {
                C[nt][0] = xv0[nt].x; C[nt][1] = xv0[nt].y;
                C[nt][2] = xv1[nt].x; C[nt][3] = xv1[nt].y;
            }
        }
        // prefetch xv for t+1 (clamped; overlaps with the MMA phase)
        {
            int tn = (t + 1 < TDIM) ? (t + 1) : (TDIM - 1);
            const float* p0 = xp0 + (size_t)tn * G4;
            const float* p1 = xp1 + (size_t)tn * G4;
            #pragma unroll
            for (int nt = 0; nt < 7; nt++) {
                if (nt < NT) {
                    xv0[nt] = *(const float2*)(p0 + nt * 8);
                    xv1[nt] = *(const float2*)(p1 + nt * 8);
                }
            }
        }

        const uint32_t axh = a_b + (uint32_t)par * (uint32_t)SAB2 + a_off;

        #pragma unroll
        for (int ks = 0; ks < 7; ks++) {
            uint32_t ah[4];
            LDSM_X4(ah, axh + ks * 32);
            #pragma unroll
            for (int p = 0; p < 4; p++) {
                if (2 * p < NT) {
                    uint32_t bh[4];
                    uint32_t bo = b_base + (uint32_t)(p * 16 * SKP * 2) + ks * 32;
                    LDSM_X4(bh, wh_b + bo);
                    mma16816(C[2 * p], ah, bh);
                    if (2 * p + 1 < NT) {
                        mma16816(C[2 * p + 1], ah, bh + 2);
                    }
                }
            }
        }

        // gates -> c,h.  Lane pairs: even t4 holds (i,f), odd holds (g,o).
        #pragma unroll
        for (int nt = 0; nt < 7; nt++) {
            if (nt < NT) {
                const int u = (tstart + nt) * 2 + (t4 >> 1);
                #pragma unroll
                for (int r = 0; r < 2; r++) {
                    float p0 = C[nt][2 * r];
                    float p1 = C[nt][2 * r + 1];
                    float q0 = evn ? p0 : (p0 + p0);
                    float s  = sigm(q0);
                    float a0 = evn ? s : (s + s - 1.0f);       // even: i ; odd: g
                    float a1 = sigm(p1);                       // even: f ; odd: o
                    float pa0 = __shfl_xor_sync(0xFFFFFFFFu, a0, 1);
                    float pa1 = __shfl_xor_sync(0xFFFFFFFFu, a1, 1);
                    float iv = evn ? a0  : pa0;
                    float fv = evn ? a1  : pa1;
                    float gv = evn ? pa0 : a0;
                    float ov = evn ? pa1 : a1;
                    float cn = fmaf(fv, c[nt][r], iv * gv);
                    c[nt][r] = cn;
                    float sc = sigm(cn + cn);
                    float hv = ov * (sc + sc - 1.0f);

                    if (evn) {
                        int lrow = r ? row1 : row0;
                        AhW[lrow * SKP + u] = __float2bfloat16(hv);
                        if (mode == 1) {
                            g_h1[((size_t)(b0 + lrow) * TDIM + t) * HDIM + u] = fmaxf(hv, 0.0f);
                        } else if (t == TDIM - 1) {
                            g_last[(b0 + lrow) * HDIM + u] = fmaxf(hv, 0.0f);
                        }
                    }
                }
            }
        }
        par ^= 1;
        __syncthreads();   // h(t) visible before next step's reads
    }
}

// ---------------- head: fc(8) + softmax ----------------
__global__ void head_kernel(const float* __restrict__ wfc,
                            const float* __restrict__ bfc,
                            float* __restrict__ out)
{
    int b = blockIdx.x * blockDim.x + threadIdx.x;
    if (b >= BDIM) return;
    const float* lr = g_last + b * HDIM;
    float lo[NCLS];
    #pragma unroll
    for (int cc = 0; cc < NCLS; cc++) {
        float s = bfc[cc];
        const float* wr = wfc + cc * HDIM;
        for (int u = 0; u < HDIM; u++) s = fmaf(lr[u], wr[u], s);
        lo[cc] = s;
    }
    float m = lo[0];
    #pragma unroll
    for (int cc = 1; cc < NCLS; cc++) m = fmaxf(m, lo[cc]);
    float sum = 0.0f;
    #pragma unroll
    for (int cc = 0; cc < NCLS; cc++) { lo[cc] = __expf(lo[cc] - m); sum += lo[cc]; }
    float inv = __fdividef(1.0f, sum);
    #pragma unroll
    for (int cc = 0; cc < NCLS; cc++) out[b * NCLS + cc] = lo[cc] * inv;
}

// ---------------- launch ----------------
extern "C" void kernel_launch(void* const* d_in, const int* in_sizes, int n_in,
                              void* d_out, int out_size)
{
    (void)in_sizes; (void)n_in; (void)out_size;
    const float* x     = (const float*)d_in[0];
    const float* w_ih1 = (const float*)d_in[1];
    const float* w_hh1 = (const float*)d_in[2];
    const float* b_ih1 = (const float*)d_in[3];
    const float* b_hh1 = (const float*)d_in[4];
    const float* w_ih2 = (const float*)d_in[5];
    const float* w_hh2 = (const float*)d_in[6];
    const float* b_ih2 = (const float*)d_in[7];
    const float* b_hh2 = (const float*)d_in[8];
    const float* w_fc  = (const float*)d_in[9];
    const float* b_fc  = (const float*)d_in[10];

    // smem: 1024 + (208*SKPX*2) + 4*(128*SKPX*2)
    const int SZ64  = 1024 + (208 * 72  * 2) + 4 * (128 * 72  * 2);  // 104704
    const int SZ112 = 1024 + (208 * 120 * 2) + 4 * (128 * 120 * 2); // 173824
    const int SSC   = SWB + 2 * SAB2;                                // 103680

    cudaFuncSetAttribute((const void*)xproj_mma2<64, 72, 4>,
                         cudaFuncAttributeMaxDynamicSharedMemorySize, SZ64);
    cudaFuncSetAttribute((const void*)xproj_mma2<112, 120, 7>,
                         cudaFuncAttributeMaxDynamicSharedMemorySize, SZ112);
    cudaFuncSetAttribute((const void*)lstm_scan_mma,
                         cudaFuncAttributeMaxDynamicSharedMemorySize, SSC);

    void *xhi, *xlo, *hhi, *hlo;
    cudaGetSymbolAddress(&xhi, g_xhi);
    cudaGetSymbolAddress(&xlo, g_xlo);
    cudaGetSymbolAddress(&hhi, g_hhi);
    cudaGetSymbolAddress(&hlo, g_hlo);

    // prepass: x -> bf16 hi/lo
    prep_kernel<<<1024, 256>>>(x);
    // layer 1
    xproj_mma2<64, 72, 4><<<148, 256, SZ64>>>(
        (const __nv_bfloat16*)xhi, (const __nv_bfloat16*)xlo, w_ih1, 64, b_ih1, b_hh1);
    lstm_scan_mma<<<256, 256, SSC>>>(w_hh1, 1);
    // between layers: h1 fp32 -> bf16 hi/lo (+pad)
    prep2_kernel<<<1024, 256>>>();
    // layer 2
    xproj_mma2<112, 120, 7><<<148, 256, SZ112>>>(
        (const __nv_bfloat16*)hhi, (const __nv_bfloat16*)hlo, w_ih2, 100, b_ih2, b_hh2);
    lstm_scan_mma<<<256, 256, SSC>>>(w_hh2, 2);
    // head
    head_kernel<<<(BDIM + 255) / 256, 256>>>(w_fc, b_fc, (float*)d_out);
}